// round 1
// baseline (speedup 1.0000x reference)
#include <cuda_runtime.h>

#define HW   512
#define NPIX (512*512)

// ---------------- scratch (no allocations allowed) ----------------
__device__ float g_t[16*NPIX];                 // erode conv scratch (8 pred + 8 gt)
__device__ float g_pe1[8*NPIX], g_pe2[8*NPIX];
__device__ float g_ge1[8*NPIX], g_ge2[8*NPIX];
__device__ int   g_tmax[4];                    // conv-max per erode level x {pred,gt}
__device__ int   g_vmax[6];                    // tensor max: pmax[0..2], gmax[0..2]
__device__ float g_partial[48*256];            // per-block partial loss sums

// ---------------- compile-time binary mask ----------------
__host__ __device__ constexpr unsigned long long BM(const char* s){
    unsigned long long m = 0;
    for (int i = 0; s[i]; ++i) if (s[i] == '1') m |= 1ULL << i;
    return m;
}

__device__ __forceinline__ float sigm(float z){
    return __fdividef(1.0f, 1.0f + __expf(-z));
}

// shared P tile geometry
#define SPN 39
#define SPP 40
#define SSN 34
#define SSP 35
#define NT  256
#define TS  32

// dot(window, binary mask) — mask is compile-time, zero terms eliminated.
// w points at sP[sy*SPP+sx]; element (r,c) of the 6x6 window = w[r*SPP+c].
template<unsigned long long M, int K, int RO>
__device__ __forceinline__ float ncdot(const float* w){
    float a = 0.f;
#pragma unroll
    for (int di = 0; di < K; ++di)
#pragma unroll
        for (int dj = 0; dj < K; ++dj)
            if ((M >> (di*K + dj)) & 1ULL)
                a += w[(di+RO)*SPP + (dj+RO)];
    return a;
}

__device__ __forceinline__ float term(float nc){
    float z = -10.f * (nc - 1.f);
    z = fminf(fmaxf(z, -10.f), 10.f);
    return sigm(z);
}

__device__ __forceinline__ float eval_S(const float* w){
    float S = 0.f;
#define T3(s) S += term(ncdot<BM(s),3,2>(w));
#define T4(s) S += term(ncdot<BM(s),4,1>(w));
#define T5(s) S += term(ncdot<BM(s),5,1>(w));
#define T6(s) S += term(ncdot<BM(s),6,0>(w));
    T3("111001111") T3("111101101") T3("111100111") T3("101101111")
    T3("011101111") T3("111101011") T3("111101110") T3("110101111")
    T4("0011000110011111") T4("1100100010011111") T4("1111100100010011") T4("1111100110001100")
    T4("1001100110011111") T4("1111000100011111") T4("1111100110011001") T4("1111100010001111")
    T5("0001100001000011000111111") T5("1100010000100001000111111")
    T5("1111110001100001000011000") T5("1111110001000010000100011")
    T5("1111110000100001000011111") T5("1111100001000010000111111")
    T5("1111110001100011000110001") T5("1000110001100011000111111")
    T6("000011000001000001000001100001111111") T6("110000100000100000100000100001111111")
    T6("111111100001100000100000100000110000") T6("111111100001000001000001000001000011")
    T6("111111100000100000100000100000111111") T6("111111000001000001000001000001111111")
    T6("111111100001100001100001100001100001")
#undef T3
#undef T4
#undef T5
#undef T6
    return S;
}

// ---------------- init ----------------
__global__ void init_kernel(){
    int t = threadIdx.x;
    if (t < 4) g_tmax[t] = 0;
    if (t < 6) g_vmax[t] = 0;
}

// ---------------- level-0 global max ----------------
__global__ __launch_bounds__(256) void max0_kernel(const float* __restrict__ p,
                                                   const float* __restrict__ g){
    __shared__ float sR[256];
    const float* src = (blockIdx.y == 0) ? p : g;
    int base = blockIdx.x * 1024;
    float m = 0.f;  // inputs are nonnegative
#pragma unroll
    for (int k = 0; k < 4; ++k) m = fmaxf(m, src[base + k*256 + threadIdx.x]);
    sR[threadIdx.x] = m; __syncthreads();
    for (int o = 128; o > 0; o >>= 1){
        if (threadIdx.x < o) sR[threadIdx.x] = fmaxf(sR[threadIdx.x], sR[threadIdx.x+o]);
        __syncthreads();
    }
    if (threadIdx.x == 0)
        atomicMax(&g_vmax[blockIdx.y == 0 ? 0 : 3], __float_as_int(sR[0]));
}

// ---------------- erosion: cross conv + global max of conv ----------------
__global__ __launch_bounds__(256) void erode_conv(const float* __restrict__ psrc,
                                                  const float* __restrict__ gsrc,
                                                  int lvl){
    __shared__ float sR[256];
    int img = blockIdx.y;   // 0..15 (8 pred, 8 gt)
    const float* src;
    if (lvl == 1) src = (img < 8) ? psrc + img*NPIX : gsrc + (img-8)*NPIX;
    else          src = (img < 8) ? g_pe1 + img*NPIX : g_ge1 + (img-8)*NPIX;
    int idx = blockIdx.x*256 + threadIdx.x;
    int y = idx >> 9, x = idx & 511;
    float t = 0.f;
    if (y > 0)      t += src[idx - HW];
    if (y < HW-1)   t += src[idx + HW];
    if (x > 0)      t += src[idx - 1];
    if (x < HW-1)   t += src[idx + 1];
    g_t[img*NPIX + idx] = t;
    sR[threadIdx.x] = t; __syncthreads();
    for (int o = 128; o > 0; o >>= 1){
        if (threadIdx.x < o) sR[threadIdx.x] = fmaxf(sR[threadIdx.x], sR[threadIdx.x+o]);
        __syncthreads();
    }
    if (threadIdx.x == 0)
        atomicMax(&g_tmax[2*(lvl-1) + (img < 8 ? 0 : 1)], __float_as_int(sR[0]));
}

// ---------------- erosion: normalize + sigmoid + tensor max ----------------
__global__ __launch_bounds__(256) void erode_finish(int lvl){
    __shared__ float sR[256];
    int img = blockIdx.y;
    int idx = blockIdx.x*256 + threadIdx.x;
    float tmax = __int_as_float(g_tmax[2*(lvl-1) + (img < 8 ? 0 : 1)]);
    float t = g_t[img*NPIX + idx];
    float v = sigm(10.f * (t / (tmax + 1e-8f) - 0.7f));
    float* dst;
    if (lvl == 1) dst = (img < 8) ? g_pe1 + img*NPIX : g_ge1 + (img-8)*NPIX;
    else          dst = (img < 8) ? g_pe2 + img*NPIX : g_ge2 + (img-8)*NPIX;
    dst[idx] = v;
    sR[threadIdx.x] = v; __syncthreads();
    for (int o = 128; o > 0; o >>= 1){
        if (threadIdx.x < o) sR[threadIdx.x] = fmaxf(sR[threadIdx.x], sR[threadIdx.x+o]);
        __syncthreads();
    }
    if (threadIdx.x == 0)
        atomicMax(&g_vmax[(img < 8 ? 0 : 3) + lvl], __float_as_int(sR[0]));
}

// ---------------- fused cp_map + dilate + squared-diff ----------------
// grid: (16, 16, 48)  z = pairtype*8 + batch,  pairtype = level*2 + inv
__global__ __launch_bounds__(NT) void cp_diff_kernel(const float* __restrict__ pred0,
                                                     const float* __restrict__ gt0){
    __shared__ float sP[SPN*SPP];
    __shared__ float sS[SSN*SSP];
    __shared__ float sR[NT];
    const int tid = threadIdx.x;
    const int pt  = blockIdx.z >> 3;
    const int b   = blockIdx.z & 7;
    const int level = pt >> 1;
    const int inv   = pt & 1;
    const int oy = blockIdx.y * TS, ox = blockIdx.x * TS;

    float cp[2][4];
    for (int ts = 0; ts < 2; ++ts){
        const float* base = (ts == 0)
            ? (level == 0 ? pred0 : (level == 1 ? g_pe1 : g_pe2))
            : (level == 0 ? gt0   : (level == 1 ? g_ge1 : g_ge2));
        const float* src = base + b*NPIX;
        float vmax = inv ? __int_as_float(g_vmax[(ts ? 3 : 0) + level]) : 0.f;

        // Load padded tile: Q(y,x) = u for interior, 1.0 on the 1-px pad ring, 0 beyond.
        for (int idx = tid; idx < SPN*SPN; idx += NT){
            int a = idx / SPN, c = idx - a*SPN;
            int qy = oy - 4 + a, qx = ox - 4 + c;
            float v;
            if (qy < -1 || qy > HW || qx < -1 || qx > HW) v = 0.f;
            else if (qy == -1 || qy == HW || qx == -1 || qx == HW) v = 1.f;
            else { float u = src[qy*HW + qx]; v = inv ? vmax - u : u; }
            sP[a*SPP + c] = v;
        }
        __syncthreads();

        // sigmoid critical-point map on tile + 1-px dilate halo (zero outside image)
        for (int idx = tid; idx < SSN*SSN; idx += NT){
            int sy = idx / SSN, sx = idx - sy*SSN;   // 0..33 ; global y = oy+sy-1
            int gy = oy + sy - 1, gx = ox + sx - 1;
            float sval = 0.f;
            if ((unsigned)gy < HW && (unsigned)gx < HW){
                const float* w = &sP[sy*SPP + sx];
                float S  = eval_S(w);
                float c0 = w[3*SPP + 3];             // center pixel value
                sval = sigm(10.f * (c0*S - 0.5f));
            }
            sS[sy*SSP + sx] = sval;
        }
        __syncthreads();

        // dilate (3x3 box, clip [0,1]); 4 output pixels per thread
#pragma unroll
        for (int q = 0; q < 4; ++q){
            int ly = (tid >> 5) + q*8, lx = tid & 31;
            float acc = 0.f;
#pragma unroll
            for (int dy = 0; dy < 3; ++dy)
#pragma unroll
                for (int dx = 0; dx < 3; ++dx)
                    acc += sS[(ly+dy)*SSP + lx + dx];
            cp[ts][q] = fminf(fmaxf(acc, 0.f), 1.f);
        }
        __syncthreads();
    }

    float local = 0.f;
#pragma unroll
    for (int q = 0; q < 4; ++q){
        float d = cp[0][q] - cp[1][q];
        local += d*d;
    }
    sR[tid] = local; __syncthreads();
    for (int o = NT/2; o > 0; o >>= 1){
        if (tid < o) sR[tid] += sR[tid+o];
        __syncthreads();
    }
    if (tid == 0)
        g_partial[(blockIdx.z*16 + blockIdx.y)*16 + blockIdx.x] = sR[0];
}

// ---------------- deterministic final reduction ----------------
__global__ __launch_bounds__(256) void final_kernel(float* out){
    __shared__ double sh[256];
    double a = 0.0;
    for (int i = threadIdx.x; i < 48*256; i += 256) a += (double)g_partial[i];
    sh[threadIdx.x] = a; __syncthreads();
    for (int o = 128; o > 0; o >>= 1){
        if (threadIdx.x < o) sh[threadIdx.x] += sh[threadIdx.x+o];
        __syncthreads();
    }
    if (threadIdx.x == 0) out[0] = (float)(sh[0] * 0.125);   // / batch (8)
}

// ---------------- launch ----------------
extern "C" void kernel_launch(void* const* d_in, const int* in_sizes, int n_in,
                              void* d_out, int out_size){
    const float* pred = (const float*)d_in[0];
    const float* gt   = (const float*)d_in[1];
    float* out = (float*)d_out;
    (void)in_sizes; (void)n_in; (void)out_size;   // num_erosions fixed at 2

    init_kernel<<<1, 32>>>();
    max0_kernel<<<dim3(2048, 2), 256>>>(pred, gt);
    erode_conv  <<<dim3(1024, 16), 256>>>(pred, gt, 1);
    erode_finish<<<dim3(1024, 16), 256>>>(1);
    erode_conv  <<<dim3(1024, 16), 256>>>(pred, gt, 2);
    erode_finish<<<dim3(1024, 16), 256>>>(2);
    cp_diff_kernel<<<dim3(16, 16, 48), 256>>>(pred, gt);
    final_kernel<<<1, 256>>>(out);
}

// round 2
// speedup vs baseline: 1.0924x; 1.0924x over previous
#include <cuda_runtime.h>

#define HW   512
#define NPIX (512*512)

// ---------------- scratch (no allocations allowed) ----------------
__device__ float g_pe1[8*NPIX], g_pe2[8*NPIX];
__device__ float g_ge1[8*NPIX], g_ge2[8*NPIX];
__device__ int   g_tmax[4];                    // conv-max per erode level x {pred,gt}
__device__ int   g_vmax[6];                    // tensor max: pmax[0..2], gmax[0..2]
__device__ float g_partial[48*256];            // per-block partial loss sums

#define L2E 14.4269504f   // 10 * log2(e)

__device__ __forceinline__ float ex2a(float x){ float r; asm("ex2.approx.ftz.f32 %0, %1;" : "=f"(r) : "f"(x)); return r; }
__device__ __forceinline__ float rcpa(float x){ float r; asm("rcp.approx.ftz.f32 %0, %1;" : "=f"(r) : "f"(x)); return r; }

__device__ __forceinline__ float sigm(float z){
    return __fdividef(1.0f, 1.0f + __expf(-z));
}

// shared P tile geometry
#define SPN 39
#define SPP 40
#define SSN 34
#define SSP 35
#define NT  256
#define TS  32

// ---------------- eval_S: 31 binary-mask "neighbor count" sigmoids ----------------
// w points at window origin; element (r,c) = w[r*SPP+c], r,c in 0..5.
__device__ __forceinline__ float eval_S(const float* __restrict__ w, float TLO){
#define W(r,c) w[(r)*SPP+(c)]
    float S = 0.f;
    const unsigned am = __activemask();

    auto TERM = [&](float nc){
        if (__all_sync(am, nc >= 2.0f)) {
            S += TLO;                                   // z clips to +10 exactly
        } else if (__all_sync(am, nc <= 0.3f)) {
            S += 1.f - ex2a(L2E*nc - L2E);              // 1/(1+e)=1-e+O(e^2), e<=9.1e-4
        } else {
            float u = fminf(fmaxf(L2E*nc - L2E, -L2E), L2E);
            S += rcpa(1.f + ex2a(u));
        }
    };

    // ---- K3 masks (window rows/cols 2..4) ----
    {
        float a2=W(2,2), b2=W(2,3), c2=W(2,4);
        float a3=W(3,2), b3=W(3,3), c3=W(3,4); (void)b3;
        float a4=W(4,2), b4=W(4,3), c4=W(4,4);
        float r2_110=a2+b2, r2_111=r2_110+c2, r2_101=a2+c2, r2_011=b2+c2;
        float r3_101=a3+c3;
        float r4_110=a4+b4, r4_111=r4_110+c4, r4_101=a4+c4, r4_011=b4+c4;
        TERM(r2_111 + c3     + r4_111);   // 111 001 111
        TERM(r2_111 + r3_101 + r4_101);   // 111 101 101
        TERM(r2_111 + a3     + r4_111);   // 111 100 111
        TERM(r2_101 + r3_101 + r4_111);   // 101 101 111
        TERM(r2_011 + r3_101 + r4_111);   // 011 101 111
        TERM(r2_111 + r3_101 + r4_011);   // 111 101 011
        TERM(r2_111 + r3_101 + r4_110);   // 111 101 110
        TERM(r2_110 + r3_101 + r4_111);   // 110 101 111
    }
    // ---- K4 masks (rows/cols 1..4) ----
    {
        float a1=W(1,1),b1=W(1,2),c1=W(1,3),d1=W(1,4);
        float a2=W(2,1),d2=W(2,4);
        float a3=W(3,1),d3=W(3,4);
        float a4=W(4,1),b4=W(4,2),c4=W(4,3),d4=W(4,4);
        float r1_0011=c1+d1, r1_1100=a1+b1, r1_1111=r1_0011+r1_1100, r1_1001=a1+d1;
        float r2_1001=a2+d2, r3_1001=a3+d3;
        float r4_0011=c4+d4, r4_1100=a4+b4, r4_1111=r4_0011+r4_1100, r4_1001=a4+d4;
        float t23=r2_1001+r3_1001;
        TERM(r1_0011 + d2 + r3_1001 + r4_1111);   // 0011 0001 1001 1111
        TERM(r1_1100 + a2 + r3_1001 + r4_1111);   // 1100 1000 1001 1111
        TERM(r1_1111 + r2_1001 + d3 + r4_0011);   // 1111 1001 0001 0011
        TERM(r1_1111 + r2_1001 + a3 + r4_1100);   // 1111 1001 1000 1100
        TERM(r1_1001 + t23 + r4_1111);            // 1001 1001 1001 1111
        TERM(r1_1111 + d2 + d3 + r4_1111);        // 1111 0001 0001 1111
        TERM(r1_1111 + t23 + r4_1001);            // 1111 1001 1001 1001
        TERM(r1_1111 + a2 + a3 + r4_1111);        // 1111 1000 1000 1111
    }
    // ---- K5 masks (rows/cols 1..5) ----
    {
        float a1=W(1,1),b1=W(1,2),c1=W(1,3),d1=W(1,4),e1=W(1,5);
        float a2=W(2,1),e2=W(2,5);
        float a3=W(3,1),e3=W(3,5);
        float a4=W(4,1),e4=W(4,5);
        float a5=W(5,1),b5=W(5,2),c5=W(5,3),d5=W(5,4),e5=W(5,5);
        float r1_00011=d1+e1, r1_11000=a1+b1, r1_11111=r1_11000+c1+r1_00011, r1_10001=a1+e1;
        float r2_s=a2+e2, r3_s=a3+e3, r4_s=a4+e4;
        float r5_00011=d5+e5, r5_11000=a5+b5, r5_11111=r5_11000+c5+r5_00011, r5_10001=a5+e5;
        float t23a=a2+a3, t23e=e2+e3, t234s=r2_s+r3_s+r4_s;
        TERM(r1_00011 + t23e + r4_s + r5_11111);     // 00011 00001 00001 10001 11111
        TERM(r1_11000 + t23a + r4_s + r5_11111);     // 11000 10000 10000 10001 11111
        TERM(r1_11111 + r2_s + a3 + a4 + r5_11000);  // 11111 10001 10000 10000 11000
        TERM(r1_11111 + r2_s + e3 + e4 + r5_00011);  // 11111 10001 00001 00001 00011
        TERM(r1_11111 + t23a + a4 + r5_11111);       // 11111 10000 10000 10000 11111
        TERM(r1_11111 + t23e + e4 + r5_11111);       // 11111 00001 00001 00001 11111
        TERM(r1_11111 + t234s + r5_10001);           // 11111 10001 10001 10001 10001
        TERM(r1_10001 + t234s + r5_11111);           // 10001 10001 10001 10001 11111
    }
    // ---- K6 masks (rows/cols 0..5) ----
    {
        float a0=W(0,0),b0=W(0,1),c0=W(0,2),d0=W(0,3),e0=W(0,4),f0=W(0,5);
        float a1=W(1,0),f1=W(1,5);
        float a2=W(2,0),f2=W(2,5);
        float a3=W(3,0),f3=W(3,5);
        float a4=W(4,0),f4=W(4,5);
        float a5=W(5,0),b5=W(5,1),c5=W(5,2),d5=W(5,3),e5=W(5,4),f5=W(5,5);
        float r0_000011=e0+f0, r0_110000=a0+b0, r0_111111=r0_110000+(c0+d0)+r0_000011;
        float r5_000011=e5+f5, r5_110000=a5+b5, r5_111111=r5_110000+(c5+d5)+r5_000011, r5_s=a5+f5;
        float r1_s=a1+f1, r2_s=a2+f2, r3_s=a3+f3, r4_s=a4+f4;
        float t23a=a2+a3, t123a=a1+t23a, t234a=t23a+a4;
        float t23f=f2+f3, t123f=f1+t23f, t234f=t23f+f4;
        TERM(r0_000011 + t123f + r4_s + r5_111111);            // 000011 000001x3 100001 111111
        TERM(r0_110000 + t123a + r4_s + r5_111111);            // 110000 100000x3 100001 111111
        TERM(r0_111111 + r1_s + t234a + r5_110000);            // 111111 100001 100000x3 110000
        TERM(r0_111111 + r1_s + t234f + r5_000011);            // 111111 100001 000001x3 000011
        TERM(r0_111111 + t123a + a4 + r5_111111);              // 111111 100000x4 111111
        TERM(r0_111111 + t123f + f4 + r5_111111);              // 111111 000001x4 111111
        TERM(r0_111111 + (r1_s+r2_s) + (r3_s+r4_s) + r5_s);    // 111111 100001x5
    }
#undef W
    return S;
}

// ---------------- init ----------------
__global__ void init_kernel(){
    int t = threadIdx.x;
    if (t < 4) g_tmax[t] = 0;
    if (t < 6) g_vmax[t] = 0;
}

__device__ __forceinline__ float blockmax(float m, float* sW, int tid){
#pragma unroll
    for (int o = 16; o > 0; o >>= 1) m = fmaxf(m, __shfl_xor_sync(0xffffffffu, m, o));
    if ((tid & 31) == 0) sW[tid >> 5] = m;
    __syncthreads();
    if (tid == 0){
#pragma unroll
        for (int i = 1; i < 8; ++i) m = fmaxf(m, sW[i]);
    }
    return m;  // valid in tid 0 only
}

// ---------------- erosion pass A: conv max (+ raw max at level 1) ----------------
// grid (256, 16), 256 threads, 4 px/thread
__global__ __launch_bounds__(256) void erode_max(const float* __restrict__ psrc,
                                                 const float* __restrict__ gsrc,
                                                 int lvl){
    __shared__ float sW[8], sW2[8];
    const int img = blockIdx.y;
    const float* src;
    if (lvl == 1) src = (img < 8) ? psrc + img*NPIX : gsrc + (img-8)*NPIX;
    else          src = (img < 8) ? g_pe1 + img*NPIX : g_ge1 + (img-8)*NPIX;
    const int tid = threadIdx.x;
    float mt = 0.f, mr = 0.f;
#pragma unroll
    for (int k = 0; k < 4; ++k){
        int idx = blockIdx.x*1024 + k*256 + tid;
        int y = idx >> 9, x = idx & 511;
        float t = 0.f;
        if (y > 0)    t += src[idx - HW];
        if (y < HW-1) t += src[idx + HW];
        if (x > 0)    t += src[idx - 1];
        if (x < HW-1) t += src[idx + 1];
        mt = fmaxf(mt, t);
        if (lvl == 1) mr = fmaxf(mr, src[idx]);
    }
    // two reductions
#pragma unroll
    for (int o = 16; o > 0; o >>= 1){
        mt = fmaxf(mt, __shfl_xor_sync(0xffffffffu, mt, o));
        mr = fmaxf(mr, __shfl_xor_sync(0xffffffffu, mr, o));
    }
    if ((tid & 31) == 0){ sW[tid>>5] = mt; sW2[tid>>5] = mr; }
    __syncthreads();
    if (tid == 0){
#pragma unroll
        for (int i = 1; i < 8; ++i){ mt = fmaxf(mt, sW[i]); mr = fmaxf(mr, sW2[i]); }
        atomicMax(&g_tmax[2*(lvl-1) + (img < 8 ? 0 : 1)], __float_as_int(mt));
        if (lvl == 1) atomicMax(&g_vmax[img < 8 ? 0 : 3], __float_as_int(mr));
    }
}

// ---------------- erosion pass B: recompute conv, normalize + sigmoid + tensor max ----------------
__global__ __launch_bounds__(256) void erode_finish(const float* __restrict__ psrc,
                                                    const float* __restrict__ gsrc,
                                                    int lvl){
    __shared__ float sW[8];
    const int img = blockIdx.y;
    const float* src;
    float* dst;
    if (lvl == 1){ src = (img < 8) ? psrc + img*NPIX : gsrc + (img-8)*NPIX;
                   dst = (img < 8) ? g_pe1 + img*NPIX : g_ge1 + (img-8)*NPIX; }
    else         { src = (img < 8) ? g_pe1 + img*NPIX : g_ge1 + (img-8)*NPIX;
                   dst = (img < 8) ? g_pe2 + img*NPIX : g_ge2 + (img-8)*NPIX; }
    const int tid = threadIdx.x;
    const float tmax = __int_as_float(g_tmax[2*(lvl-1) + (img < 8 ? 0 : 1)]);
    float mv = 0.f;
#pragma unroll
    for (int k = 0; k < 4; ++k){
        int idx = blockIdx.x*1024 + k*256 + tid;
        int y = idx >> 9, x = idx & 511;
        float t = 0.f;
        if (y > 0)    t += src[idx - HW];
        if (y < HW-1) t += src[idx + HW];
        if (x > 0)    t += src[idx - 1];
        if (x < HW-1) t += src[idx + 1];
        float v = sigm(10.f * (t / (tmax + 1e-8f) - 0.7f));
        dst[idx] = v;
        mv = fmaxf(mv, v);
    }
    float m = blockmax(mv, sW, tid);
    if (tid == 0)
        atomicMax(&g_vmax[(img < 8 ? 0 : 3) + lvl], __float_as_int(m));
}

// ---------------- fused cp_map + dilate + squared-diff ----------------
// grid: (16, 16, 48)  z = pairtype*8 + batch,  pairtype = level*2 + inv
__global__ __launch_bounds__(NT) void cp_diff_kernel(const float* __restrict__ pred0,
                                                     const float* __restrict__ gt0){
    __shared__ float sP[SPN*SPP];
    __shared__ float sS[SSN*SSP];
    __shared__ float sR[NT];
    const int tid = threadIdx.x;
    const int pt  = blockIdx.z >> 3;
    const int b   = blockIdx.z & 7;
    const int level = pt >> 1;
    const int inv   = pt & 1;
    const int oy = blockIdx.y * TS, ox = blockIdx.x * TS;
    const float TLO = rcpa(1.f + ex2a(L2E));   // 1/(1+e^10), matches saturated slow path

    float cp[2][4];
    for (int ts = 0; ts < 2; ++ts){
        const float* base = (ts == 0)
            ? (level == 0 ? pred0 : (level == 1 ? g_pe1 : g_pe2))
            : (level == 0 ? gt0   : (level == 1 ? g_ge1 : g_ge2));
        const float* src = base + b*NPIX;
        float vmax = inv ? __int_as_float(g_vmax[(ts ? 3 : 0) + level]) : 0.f;

        // Load padded tile: Q(y,x) = u for interior, 1.0 on the 1-px pad ring, 0 beyond.
        for (int idx = tid; idx < SPN*SPN; idx += NT){
            int a = idx / SPN, c = idx - a*SPN;
            int qy = oy - 4 + a, qx = ox - 4 + c;
            float v;
            if (qy < -1 || qy > HW || qx < -1 || qx > HW) v = 0.f;
            else if (qy == -1 || qy == HW || qx == -1 || qx == HW) v = 1.f;
            else { float u = src[qy*HW + qx]; v = inv ? vmax - u : u; }
            sP[a*SPP + c] = v;
        }
        __syncthreads();

        // sigmoid critical-point map on tile + 1-px dilate halo (zero outside image)
        for (int idx = tid; idx < SSN*SSN; idx += NT){
            int sy = idx / SSN, sx = idx - sy*SSN;   // 0..33 ; global y = oy+sy-1
            int gy = oy + sy - 1, gx = ox + sx - 1;
            float sval = 0.f;
            if ((unsigned)gy < HW && (unsigned)gx < HW){
                const float* w = &sP[sy*SPP + sx];
                float S  = eval_S(w, TLO);
                float c0 = w[3*SPP + 3];             // center pixel value
                sval = sigm(10.f * (c0*S - 0.5f));
            }
            sS[sy*SSP + sx] = sval;
        }
        __syncthreads();

        // dilate (3x3 box, clip [0,1]); 4 output pixels per thread
#pragma unroll
        for (int q = 0; q < 4; ++q){
            int ly = (tid >> 5) + q*8, lx = tid & 31;
            float acc = 0.f;
#pragma unroll
            for (int dy = 0; dy < 3; ++dy)
#pragma unroll
                for (int dx = 0; dx < 3; ++dx)
                    acc += sS[(ly+dy)*SSP + lx + dx];
            cp[ts][q] = fminf(fmaxf(acc, 0.f), 1.f);
        }
        __syncthreads();
    }

    float local = 0.f;
#pragma unroll
    for (int q = 0; q < 4; ++q){
        float d = cp[0][q] - cp[1][q];
        local += d*d;
    }
    sR[tid] = local; __syncthreads();
    for (int o = NT/2; o > 0; o >>= 1){
        if (tid < o) sR[tid] += sR[tid+o];
        __syncthreads();
    }
    if (tid == 0)
        g_partial[(blockIdx.z*16 + blockIdx.y)*16 + blockIdx.x] = sR[0];
}

// ---------------- deterministic final reduction ----------------
__global__ __launch_bounds__(256) void final_kernel(float* out){
    __shared__ double sh[256];
    double a = 0.0;
    for (int i = threadIdx.x; i < 48*256; i += 256) a += (double)g_partial[i];
    sh[threadIdx.x] = a; __syncthreads();
    for (int o = 128; o > 0; o >>= 1){
        if (threadIdx.x < o) sh[threadIdx.x] += sh[threadIdx.x+o];
        __syncthreads();
    }
    if (threadIdx.x == 0) out[0] = (float)(sh[0] * 0.125);   // / batch (8)
}

// ---------------- launch ----------------
extern "C" void kernel_launch(void* const* d_in, const int* in_sizes, int n_in,
                              void* d_out, int out_size){
    const float* pred = (const float*)d_in[0];
    const float* gt   = (const float*)d_in[1];
    float* out = (float*)d_out;
    (void)in_sizes; (void)n_in; (void)out_size;   // num_erosions fixed at 2

    init_kernel<<<1, 32>>>();                         // launch 1
    erode_max   <<<dim3(256, 16), 256>>>(pred, gt, 1);// launch 2
    erode_finish<<<dim3(256, 16), 256>>>(pred, gt, 1);// launch 3
    erode_max   <<<dim3(256, 16), 256>>>(pred, gt, 2);// launch 4
    erode_finish<<<dim3(256, 16), 256>>>(pred, gt, 2);// launch 5
    cp_diff_kernel<<<dim3(16, 16, 48), 256>>>(pred, gt); // launch 6 (ncu -s 5 lands here)
    final_kernel<<<1, 256>>>(out);                    // launch 7
}

// round 3
// speedup vs baseline: 1.3535x; 1.2390x over previous
#include <cuda_runtime.h>

#define HW   512
#define NPIX (512*512)

// ---------------- scratch (no allocations allowed) ----------------
__device__ float g_pe1[8*NPIX], g_pe2[8*NPIX];
__device__ float g_ge1[8*NPIX], g_ge2[8*NPIX];
__device__ int   g_tmax[4];
__device__ int   g_vmax[6];
__device__ float g_partial[48*256];

#define L2E 14.4269504f   // 10 * log2(e)

__device__ __forceinline__ float ex2a(float x){ float r; asm("ex2.approx.ftz.f32 %0, %1;" : "=f"(r) : "f"(x)); return r; }
__device__ __forceinline__ float rcpa(float x){ float r; asm("rcp.approx.ftz.f32 %0, %1;" : "=f"(r) : "f"(x)); return r; }
__device__ __forceinline__ float sigm(float z){
    return __fdividef(1.0f, 1.0f + __expf(-z));
}

// ---------------- packed f32x2 helpers ----------------
typedef unsigned long long pf;
__device__ __forceinline__ pf PADD(pf a, pf b){ pf r; asm("add.rn.f32x2 %0, %1, %2;" : "=l"(r) : "l"(a), "l"(b)); return r; }
__device__ __forceinline__ pf PFMA(pf a, pf b, pf c){ pf r; asm("fma.rn.f32x2 %0, %1, %2, %3;" : "=l"(r) : "l"(a), "l"(b), "l"(c)); return r; }
__device__ __forceinline__ pf PK2(float lo, float hi){ pf r; asm("mov.b64 %0, {%1, %2};" : "=l"(r) : "f"(lo), "f"(hi)); return r; }
__device__ __forceinline__ void UPK(pf a, float& lo, float& hi){ asm("mov.b64 {%0, %1}, %2;" : "=f"(lo), "=f"(hi) : "l"(a)); }

// sigmoid terms: t = 1/(1+2^u), u = L2E*nc - L2E (unclamped; inf -> 0, err<=4.6e-5)
__device__ __forceinline__ void term_rcp(pf nc2, pf& S2, pf CL2, pf CNL2){
    pf u2 = PFMA(nc2, CL2, CNL2);
    float u0, u1; UPK(u2, u0, u1);
    float t0 = rcpa(1.f + ex2a(u0));
    float t1 = rcpa(1.f + ex2a(u1));
    S2 = PADD(S2, PK2(t0, t1));
}
// Newton flavor: no MUFU rcp (magic seed + 2 NR), clamp u to avoid inf seed.
__device__ __forceinline__ void term_nr(pf nc2, pf& S2, pf CL2, pf CNL2){
    pf u2 = PFMA(nc2, CL2, CNL2);
    float u0, u1; UPK(u2, u0, u1);
    float f0 = 1.f + ex2a(fminf(u0, 14.f));
    float f1 = 1.f + ex2a(fminf(u1, 14.f));
    float r0 = __int_as_float(0x7EF311C3 - __float_as_int(f0));
    float r1 = __int_as_float(0x7EF311C3 - __float_as_int(f1));
    r0 = r0*(2.f - f0*r0); r1 = r1*(2.f - f1*r1);
    r0 = r0*(2.f - f0*r0); r1 = r1*(2.f - f1*r1);
    S2 = PADD(S2, PK2(r0, r1));
}

// ---------------- geometry ----------------
#define SSN 34
#define SSP 35
#define NT  256
#define TS  32
#define PK  21          // float2-pairs pitch per column (odd => conflict-free LDS.64)

// ---------------- init ----------------
__global__ void init_kernel(){
    int t = threadIdx.x;
    if (t < 4) g_tmax[t] = 0;
    if (t < 6) g_vmax[t] = 0;
}

// ---------------- erosion pass A: conv max (+ raw max at level 1) ----------------
__global__ __launch_bounds__(256) void erode_max(const float* __restrict__ psrc,
                                                 const float* __restrict__ gsrc,
                                                 int lvl){
    __shared__ float sW[8], sW2[8];
    const int img = blockIdx.y;
    const float* src;
    if (lvl == 1) src = (img < 8) ? psrc + img*NPIX : gsrc + (img-8)*NPIX;
    else          src = (img < 8) ? g_pe1 + img*NPIX : g_ge1 + (img-8)*NPIX;
    const int tid = threadIdx.x;
    float mt = 0.f, mr = 0.f;
#pragma unroll
    for (int k = 0; k < 4; ++k){
        int idx = blockIdx.x*1024 + k*256 + tid;
        int y = idx >> 9, x = idx & 511;
        float t = 0.f;
        if (y > 0)    t += src[idx - HW];
        if (y < HW-1) t += src[idx + HW];
        if (x > 0)    t += src[idx - 1];
        if (x < HW-1) t += src[idx + 1];
        mt = fmaxf(mt, t);
        if (lvl == 1) mr = fmaxf(mr, src[idx]);
    }
#pragma unroll
    for (int o = 16; o > 0; o >>= 1){
        mt = fmaxf(mt, __shfl_xor_sync(0xffffffffu, mt, o));
        mr = fmaxf(mr, __shfl_xor_sync(0xffffffffu, mr, o));
    }
    if ((tid & 31) == 0){ sW[tid>>5] = mt; sW2[tid>>5] = mr; }
    __syncthreads();
    if (tid == 0){
#pragma unroll
        for (int i = 1; i < 8; ++i){ mt = fmaxf(mt, sW[i]); mr = fmaxf(mr, sW2[i]); }
        atomicMax(&g_tmax[2*(lvl-1) + (img < 8 ? 0 : 1)], __float_as_int(mt));
        if (lvl == 1) atomicMax(&g_vmax[img < 8 ? 0 : 3], __float_as_int(mr));
    }
}

// ---------------- erosion pass B ----------------
__global__ __launch_bounds__(256) void erode_finish(const float* __restrict__ psrc,
                                                    const float* __restrict__ gsrc,
                                                    int lvl){
    __shared__ float sW[8];
    const int img = blockIdx.y;
    const float* src;
    float* dst;
    if (lvl == 1){ src = (img < 8) ? psrc + img*NPIX : gsrc + (img-8)*NPIX;
                   dst = (img < 8) ? g_pe1 + img*NPIX : g_ge1 + (img-8)*NPIX; }
    else         { src = (img < 8) ? g_pe1 + img*NPIX : g_ge1 + (img-8)*NPIX;
                   dst = (img < 8) ? g_pe2 + img*NPIX : g_ge2 + (img-8)*NPIX; }
    const int tid = threadIdx.x;
    const float tmax = __int_as_float(g_tmax[2*(lvl-1) + (img < 8 ? 0 : 1)]);
    float mv = 0.f;
#pragma unroll
    for (int k = 0; k < 4; ++k){
        int idx = blockIdx.x*1024 + k*256 + tid;
        int y = idx >> 9, x = idx & 511;
        float t = 0.f;
        if (y > 0)    t += src[idx - HW];
        if (y < HW-1) t += src[idx + HW];
        if (x > 0)    t += src[idx - 1];
        if (x < HW-1) t += src[idx + 1];
        float v = sigm(10.f * (t / (tmax + 1e-8f) - 0.7f));
        dst[idx] = v;
        mv = fmaxf(mv, v);
    }
#pragma unroll
    for (int o = 16; o > 0; o >>= 1) mv = fmaxf(mv, __shfl_xor_sync(0xffffffffu, mv, o));
    if ((tid & 31) == 0) sW[tid >> 5] = mv;
    __syncthreads();
    if (tid == 0){
#pragma unroll
        for (int i = 1; i < 8; ++i) mv = fmaxf(mv, sW[i]);
        atomicMax(&g_vmax[(img < 8 ? 0 : 3) + lvl], __float_as_int(mv));
    }
}

// ---------------- fused cp_map + dilate + squared-diff (packed f32x2) ----------------
// grid: (16, 16, 48)  z = pairtype*8 + batch,  pairtype = level*2 + inv
__global__ __launch_bounds__(NT) void cp_diff_kernel(const float* __restrict__ pred0,
                                                     const float* __restrict__ gt0){
    // fA[col][k] = (row 2k, row 2k+1); fB[col][k] = (row 2k+1, row 2k+2)
    __shared__ pf    fA[39*PK];
    __shared__ pf    fB[39*PK];
    __shared__ float sS[SSN*SSP];
    __shared__ float sR[NT];
    const int tid = threadIdx.x;
    const int pt  = blockIdx.z >> 3;
    const int b   = blockIdx.z & 7;
    const int level = pt >> 1;
    const int inv   = pt & 1;
    const int oy = blockIdx.y * TS, ox = blockIdx.x * TS;
    const pf CL2  = PK2(L2E, L2E);
    const pf CNL2 = PK2(-L2E, -L2E);

    float cp[2][4];
    for (int ts = 0; ts < 2; ++ts){
        const float* base = (ts == 0)
            ? (level == 0 ? pred0 : (level == 1 ? g_pe1 : g_pe2))
            : (level == 0 ? gt0   : (level == 1 ? g_ge1 : g_ge2));
        const float* src = base + b*NPIX;
        float vmax = inv ? __int_as_float(g_vmax[(ts ? 3 : 0) + level]) : 0.f;

        // Load padded tile transposed into the two phase-shifted pair arrays.
        float* A = (float*)fA; float* B = (float*)fB;
        for (int i = tid; i < 39*39; i += NT){
            int a = i / 39, c = i - a*39;
            int qy = oy - 4 + a, qx = ox - 4 + c;
            float v;
            if (qy < -1 || qy > HW || qx < -1 || qx > HW) v = 0.f;
            else if (qy == -1 || qy == HW || qx == -1 || qx == HW) v = 1.f;
            else { float u = src[qy*HW + qx]; v = inv ? vmax - u : u; }
            A[(c*PK + (a >> 1))*2 + (a & 1)] = v;
            if (a & 1)       B[(c*PK + (a >> 1))*2]     = v;
            else if (a >= 2) B[(c*PK + (a >> 1) - 1)*2 + 1] = v;
        }
        __syncthreads();

        // paired sites: 34 cols x 17 vertical pairs
        for (int idx = tid; idx < 34*17; idx += NT){
            int p = idx / 34, x = idx - p*34;     // pair-row p (sy=2p), col x
            // window element (r,c) pair: rows (2p+r, 2p+1+r)
#define RW(r,c) ( ((r) & 1) ? fB[(x+(c))*PK + p + ((r)>>1)] : fA[(x+(c))*PK + p + ((r)>>1)] )
            pf S2 = 0ull;  // (0.f, 0.f)
            // ---- K6 (rows 0..5, cols 0..5) ----
            {
                pf a0=RW(0,0),b0=RW(0,1),c0_=RW(0,2),d0=RW(0,3),e0=RW(0,4),f0=RW(0,5);
                pf a1=RW(1,0),f1=RW(1,5);
                pf a2=RW(2,0),f2=RW(2,5);
                pf a3=RW(3,0),f3=RW(3,5);
                pf a4=RW(4,0),f4=RW(4,5);
                pf a5=RW(5,0),b5=RW(5,1),c5=RW(5,2),d5=RW(5,3),e5=RW(5,4),f5=RW(5,5);
                pf r0_000011=PADD(e0,f0), r0_110000=PADD(a0,b0);
                pf r0_111111=PADD(PADD(r0_110000,PADD(c0_,d0)),r0_000011);
                pf r5_000011=PADD(e5,f5), r5_110000=PADD(a5,b5);
                pf r5_111111=PADD(PADD(r5_110000,PADD(c5,d5)),r5_000011), r5_s=PADD(a5,f5);
                pf r1_s=PADD(a1,f1), r2_s=PADD(a2,f2), r3_s=PADD(a3,f3), r4_s=PADD(a4,f4);
                pf t23a=PADD(a2,a3), t123a=PADD(a1,t23a), t234a=PADD(t23a,a4);
                pf t23f=PADD(f2,f3), t123f=PADD(f1,t23f), t234f=PADD(t23f,f4);
                term_nr(PADD(PADD(r0_000011,t123f),PADD(r4_s,r5_111111)), S2, CL2, CNL2);
                term_nr(PADD(PADD(r0_110000,t123a),PADD(r4_s,r5_111111)), S2, CL2, CNL2);
                term_nr(PADD(PADD(r0_111111,r1_s),PADD(t234a,r5_110000)), S2, CL2, CNL2);
                term_nr(PADD(PADD(r0_111111,r1_s),PADD(t234f,r5_000011)), S2, CL2, CNL2);
                term_nr(PADD(PADD(r0_111111,t123a),PADD(a4,r5_111111)), S2, CL2, CNL2);
                term_nr(PADD(PADD(r0_111111,t123f),PADD(f4,r5_111111)), S2, CL2, CNL2);
                term_nr(PADD(PADD(r0_111111,PADD(r1_s,r2_s)),PADD(PADD(r3_s,r4_s),r5_s)), S2, CL2, CNL2);
            }
            // ---- K5 (rows/cols 1..5) ----
            {
                pf a1=RW(1,1),b1=RW(1,2),c1=RW(1,3),d1=RW(1,4),e1=RW(1,5);
                pf a2=RW(2,1),e2=RW(2,5);
                pf a3=RW(3,1),e3=RW(3,5);
                pf a4=RW(4,1),e4=RW(4,5);
                pf a5=RW(5,1),b5=RW(5,2),c5=RW(5,3),d5=RW(5,4),e5=RW(5,5);
                pf r1_00011=PADD(d1,e1), r1_11000=PADD(a1,b1);
                pf r1_11111=PADD(PADD(r1_11000,c1),r1_00011), r1_10001=PADD(a1,e1);
                pf r2_s=PADD(a2,e2), r3_s=PADD(a3,e3), r4_s=PADD(a4,e4);
                pf r5_00011=PADD(d5,e5), r5_11000=PADD(a5,b5);
                pf r5_11111=PADD(PADD(r5_11000,c5),r5_00011), r5_10001=PADD(a5,e5);
                pf t23a=PADD(a2,a3), t23e=PADD(e2,e3), t234s=PADD(PADD(r2_s,r3_s),r4_s);
                term_nr(PADD(PADD(r1_00011,t23e),PADD(r4_s,r5_11111)), S2, CL2, CNL2);
                term_nr(PADD(PADD(r1_11000,t23a),PADD(r4_s,r5_11111)), S2, CL2, CNL2);
                term_nr(PADD(PADD(r1_11111,r2_s),PADD(PADD(a3,a4),r5_11000)), S2, CL2, CNL2);
                term_nr(PADD(PADD(r1_11111,r2_s),PADD(PADD(e3,e4),r5_00011)), S2, CL2, CNL2);
                term_nr(PADD(PADD(r1_11111,t23a),PADD(a4,r5_11111)), S2, CL2, CNL2);
                term_nr(PADD(PADD(r1_11111,t23e),PADD(e4,r5_11111)), S2, CL2, CNL2);
                term_rcp(PADD(PADD(r1_11111,t234s),r5_10001), S2, CL2, CNL2);
                term_rcp(PADD(PADD(r1_10001,t234s),r5_11111), S2, CL2, CNL2);
            }
            // ---- K4 (rows/cols 1..4) ----
            {
                pf a1=RW(1,1),b1=RW(1,2),c1=RW(1,3),d1=RW(1,4);
                pf a2=RW(2,1),d2=RW(2,4);
                pf a3=RW(3,1),d3=RW(3,4);
                pf a4=RW(4,1),b4=RW(4,2),c4=RW(4,3),d4=RW(4,4);
                pf r1_0011=PADD(c1,d1), r1_1100=PADD(a1,b1), r1_1111=PADD(r1_0011,r1_1100), r1_1001=PADD(a1,d1);
                pf r2_1001=PADD(a2,d2), r3_1001=PADD(a3,d3);
                pf r4_0011=PADD(c4,d4), r4_1100=PADD(a4,b4), r4_1111=PADD(r4_0011,r4_1100), r4_1001=PADD(a4,d4);
                pf t23=PADD(r2_1001,r3_1001);
                term_rcp(PADD(PADD(r1_0011,d2),PADD(r3_1001,r4_1111)), S2, CL2, CNL2);
                term_rcp(PADD(PADD(r1_1100,a2),PADD(r3_1001,r4_1111)), S2, CL2, CNL2);
                term_rcp(PADD(PADD(r1_1111,r2_1001),PADD(d3,r4_0011)), S2, CL2, CNL2);
                term_rcp(PADD(PADD(r1_1111,r2_1001),PADD(a3,r4_1100)), S2, CL2, CNL2);
                term_rcp(PADD(PADD(r1_1001,t23),r4_1111), S2, CL2, CNL2);
                term_rcp(PADD(PADD(r1_1111,PADD(d2,d3)),r4_1111), S2, CL2, CNL2);
                term_rcp(PADD(PADD(r1_1111,t23),r4_1001), S2, CL2, CNL2);
                term_rcp(PADD(PADD(r1_1111,PADD(a2,a3)),r4_1111), S2, CL2, CNL2);
            }
            // ---- K3 (rows/cols 2..4) ----
            {
                pf a2=RW(2,2),b2=RW(2,3),c2=RW(2,4);
                pf a3=RW(3,2),c3=RW(3,4);
                pf a4=RW(4,2),b4=RW(4,3),c4=RW(4,4);
                pf r2_110=PADD(a2,b2), r2_111=PADD(r2_110,c2), r2_101=PADD(a2,c2), r2_011=PADD(b2,c2);
                pf r3_101=PADD(a3,c3);
                pf r4_110=PADD(a4,b4), r4_111=PADD(r4_110,c4), r4_101=PADD(a4,c4), r4_011=PADD(b4,c4);
                term_rcp(PADD(PADD(r2_111,c3),r4_111), S2, CL2, CNL2);
                term_rcp(PADD(PADD(r2_111,r3_101),r4_101), S2, CL2, CNL2);
                term_rcp(PADD(PADD(r2_111,a3),r4_111), S2, CL2, CNL2);
                term_rcp(PADD(PADD(r2_101,r3_101),r4_111), S2, CL2, CNL2);
                term_rcp(PADD(PADD(r2_011,r3_101),r4_111), S2, CL2, CNL2);
                term_rcp(PADD(PADD(r2_111,r3_101),r4_011), S2, CL2, CNL2);
                term_rcp(PADD(PADD(r2_111,r3_101),r4_110), S2, CL2, CNL2);
                term_rcp(PADD(PADD(r2_110,r3_101),r4_111), S2, CL2, CNL2);
            }
            // ---- final sval for the two sites ----
            float S0, S1; UPK(S2, S0, S1);
            float c00, c01; UPK(RW(3,3), c00, c01);   // center pixels
#undef RW
            int sy = 2*p;
            int gy0 = oy + sy - 1, gx = ox + x - 1;
            float s0 = sigm(10.f*(c00*S0 - 0.5f));
            float s1 = sigm(10.f*(c01*S1 - 0.5f));
            bool okx = ((unsigned)gx < HW);
            if (!okx || (unsigned)gy0     >= HW) s0 = 0.f;
            if (!okx || (unsigned)(gy0+1) >= HW) s1 = 0.f;
            sS[sy*SSP + x]     = s0;
            sS[(sy+1)*SSP + x] = s1;
        }
        __syncthreads();

        // dilate (3x3 box, clip [0,1]); 4 output pixels per thread
#pragma unroll
        for (int q = 0; q < 4; ++q){
            int ly = (tid >> 5) + q*8, lx = tid & 31;
            float acc = 0.f;
#pragma unroll
            for (int dy = 0; dy < 3; ++dy)
#pragma unroll
                for (int dx = 0; dx < 3; ++dx)
                    acc += sS[(ly+dy)*SSP + lx + dx];
            cp[ts][q] = fminf(fmaxf(acc, 0.f), 1.f);
        }
        __syncthreads();
    }

    float local = 0.f;
#pragma unroll
    for (int q = 0; q < 4; ++q){
        float d = cp[0][q] - cp[1][q];
        local += d*d;
    }
    sR[tid] = local; __syncthreads();
    for (int o = NT/2; o > 0; o >>= 1){
        if (tid < o) sR[tid] += sR[tid+o];
        __syncthreads();
    }
    if (tid == 0)
        g_partial[(blockIdx.z*16 + blockIdx.y)*16 + blockIdx.x] = sR[0];
}

// ---------------- deterministic final reduction ----------------
__global__ __launch_bounds__(256) void final_kernel(float* out){
    __shared__ double sh[256];
    double a = 0.0;
    for (int i = threadIdx.x; i < 48*256; i += 256) a += (double)g_partial[i];
    sh[threadIdx.x] = a; __syncthreads();
    for (int o = 128; o > 0; o >>= 1){
        if (threadIdx.x < o) sh[threadIdx.x] += sh[threadIdx.x+o];
        __syncthreads();
    }
    if (threadIdx.x == 0) out[0] = (float)(sh[0] * 0.125);
}

// ---------------- launch ----------------
extern "C" void kernel_launch(void* const* d_in, const int* in_sizes, int n_in,
                              void* d_out, int out_size){
    const float* pred = (const float*)d_in[0];
    const float* gt   = (const float*)d_in[1];
    float* out = (float*)d_out;
    (void)in_sizes; (void)n_in; (void)out_size;

    init_kernel<<<1, 32>>>();
    erode_max   <<<dim3(256, 16), 256>>>(pred, gt, 1);
    erode_finish<<<dim3(256, 16), 256>>>(pred, gt, 1);
    erode_max   <<<dim3(256, 16), 256>>>(pred, gt, 2);
    erode_finish<<<dim3(256, 16), 256>>>(pred, gt, 2);
    cp_diff_kernel<<<dim3(16, 16, 48), 256>>>(pred, gt);
    final_kernel<<<1, 256>>>(out);
}

// round 4
// speedup vs baseline: 1.5994x; 1.1817x over previous
#include <cuda_runtime.h>

#define HW   512
#define NPIX (512*512)

// ---------------- scratch ----------------
__device__ float g_pe1[8*NPIX], g_pe2[8*NPIX];
__device__ float g_ge1[8*NPIX], g_ge2[8*NPIX];
__device__ int   g_tmax[4];
__device__ int   g_vmax[6];
__device__ float g_partial[7680];

#define L2E   14.4269504f    // 10*log2(e)
#define IL2E  0.069314718f   // 1/L2E

__device__ __forceinline__ float ex2a(float x){ float r; asm("ex2.approx.ftz.f32 %0, %1;" : "=f"(r) : "f"(x)); return r; }
__device__ __forceinline__ float rcpa(float x){ float r; asm("rcp.approx.ftz.f32 %0, %1;" : "=f"(r) : "f"(x)); return r; }
__device__ __forceinline__ float sigm(float z){ return __fdividef(1.0f, 1.0f + __expf(-z)); }

typedef unsigned long long pf;
__device__ __forceinline__ pf PADD(pf a, pf b){ pf r; asm("add.rn.f32x2 %0, %1, %2;" : "=l"(r) : "l"(a), "l"(b)); return r; }
__device__ __forceinline__ pf PFMA(pf a, pf b, pf c){ pf r; asm("fma.rn.f32x2 %0, %1, %2, %3;" : "=l"(r) : "l"(a), "l"(b), "l"(c)); return r; }
__device__ __forceinline__ pf PK2(float lo, float hi){ pf r; asm("mov.b64 %0, {%1, %2};" : "=l"(r) : "f"(lo), "f"(hi)); return r; }
__device__ __forceinline__ void UPK(pf a, float& lo, float& hi){ asm("mov.b64 {%0, %1}, %2;" : "=f"(lo), "=f"(hi) : "l"(a)); }

// sigmoid accumulators on a packed pre-biased argument u2 (t = 1/(1+2^u))
__device__ __forceinline__ void side_rcp(pf u2, pf& S2){
    float u0,u1; UPK(u2,u0,u1);
    S2 = PADD(S2, PK2(rcpa(1.f+ex2a(u0)), rcpa(1.f+ex2a(u1))));
}
__device__ __forceinline__ void side_nr(pf u2, pf& S2){
    float u0,u1; UPK(u2,u0,u1);
    float f0 = 1.f + ex2a(fminf(u0,14.f));
    float f1 = 1.f + ex2a(fminf(u1,14.f));
    float r0 = __int_as_float(0x7EF311C3 - __float_as_int(f0));
    float r1 = __int_as_float(0x7EF311C3 - __float_as_int(f1));
    r0 = r0*(2.f-f0*r0); r1 = r1*(2.f-f1*r1);
    r0 = r0*(2.f-f0*r0); r1 = r1*(2.f-f1*r1);
    S2 = PADD(S2, PK2(r0,r1));
}

// ---------------- geometry ----------------
#define SSN 34
#define SSP 35
#define NT  256
#define TS  32
#define PK  21

// The 31-mask add tree. RW(r,c) must be defined by the includer.
// TERM_N / TERM_R macros: (packed_tree_sum, popcount_id)
#define TREE_BODY                                                                  \
    {   /* K6 (rows 0..5, cols 0..5) */                                            \
        pf a0=RW(0,0),b0=RW(0,1),c0_=RW(0,2),d0=RW(0,3),e0=RW(0,4),f0=RW(0,5);     \
        pf a1=RW(1,0),f1=RW(1,5);                                                  \
        pf a2=RW(2,0),f2=RW(2,5);                                                  \
        pf a3=RW(3,0),f3=RW(3,5);                                                  \
        pf a4=RW(4,0),f4=RW(4,5);                                                  \
        pf a5=RW(5,0),b5=RW(5,1),c5=RW(5,2),d5=RW(5,3),e5=RW(5,4),f5=RW(5,5);      \
        pf r0_03=PADD(e0,f0), r0_30=PADD(a0,b0);                                   \
        pf r0_66=PADD(PADD(r0_30,PADD(c0_,d0)),r0_03);                             \
        pf r5_03=PADD(e5,f5), r5_30=PADD(a5,b5);                                   \
        pf r5_66=PADD(PADD(r5_30,PADD(c5,d5)),r5_03), r5_s=PADD(a5,f5);            \
        pf r1_s=PADD(a1,f1), r2_s=PADD(a2,f2), r3_s=PADD(a3,f3), r4_s=PADD(a4,f4); \
        pf t23a=PADD(a2,a3), t123a=PADD(a1,t23a), t234a=PADD(t23a,a4);             \
        pf t23f=PADD(f2,f3), t123f=PADD(f1,t23f), t234f=PADD(t23f,f4);             \
        TERM_N(PADD(PADD(r0_03,t123f),PADD(r4_s,r5_66)), 13)                       \
        TERM_N(PADD(PADD(r0_30,t123a),PADD(r4_s,r5_66)), 13)                       \
        TERM_N(PADD(PADD(r0_66,r1_s),PADD(t234a,r5_30)), 13)                       \
        TERM_N(PADD(PADD(r0_66,r1_s),PADD(t234f,r5_03)), 13)                       \
        TERM_N(PADD(PADD(r0_66,t123a),PADD(a4,r5_66)), 16)                         \
        TERM_N(PADD(PADD(r0_66,t123f),PADD(f4,r5_66)), 16)                         \
        TERM_N(PADD(PADD(r0_66,PADD(r1_s,r2_s)),PADD(PADD(r3_s,r4_s),r5_s)), 16)   \
    }                                                                              \
    {   /* K5 (rows/cols 1..5) */                                                  \
        pf a1=RW(1,1),b1=RW(1,2),c1=RW(1,3),d1=RW(1,4),e1=RW(1,5);                 \
        pf a2=RW(2,1),e2=RW(2,5);                                                  \
        pf a3=RW(3,1),e3=RW(3,5);                                                  \
        pf a4=RW(4,1),e4=RW(4,5);                                                  \
        pf a5=RW(5,1),b5=RW(5,2),c5=RW(5,3),d5=RW(5,4),e5=RW(5,5);                 \
        pf r1_02=PADD(d1,e1), r1_20=PADD(a1,b1);                                   \
        pf r1_55=PADD(PADD(r1_20,c1),r1_02), r1_s=PADD(a1,e1);                     \
        pf q2=PADD(a2,e2), q3=PADD(a3,e3), q4=PADD(a4,e4);                         \
        pf r5_02=PADD(d5,e5), r5_20=PADD(a5,b5);                                   \
        pf r5_55=PADD(PADD(r5_20,c5),r5_02), r5_s=PADD(a5,e5);                     \
        pf t23a=PADD(a2,a3), t23e=PADD(e2,e3), t234=PADD(PADD(q2,q3),q4);          \
        TERM_N(PADD(PADD(r1_02,t23e),PADD(q4,r5_55)), 11)                          \
        TERM_N(PADD(PADD(r1_20,t23a),PADD(q4,r5_55)), 11)                          \
        TERM_N(PADD(PADD(r1_55,q2),PADD(PADD(a3,a4),r5_20)), 11)                   \
        TERM_N(PADD(PADD(r1_55,q2),PADD(PADD(e3,e4),r5_02)), 11)                   \
        TERM_N(PADD(PADD(r1_55,t23a),PADD(a4,r5_55)), 13)                          \
        TERM_N(PADD(PADD(r1_55,t23e),PADD(e4,r5_55)), 13)                          \
        TERM_N(PADD(PADD(r1_55,t234),r5_s), 13)                                    \
        TERM_N(PADD(PADD(r1_s,t234),r5_55), 13)                                    \
    }                                                                              \
    {   /* K4 (rows/cols 1..4) */                                                  \
        pf a1=RW(1,1),b1=RW(1,2),c1=RW(1,3),d1=RW(1,4);                            \
        pf a2=RW(2,1),d2=RW(2,4);                                                  \
        pf a3=RW(3,1),d3=RW(3,4);                                                  \
        pf a4=RW(4,1),b4=RW(4,2),c4=RW(4,3),d4=RW(4,4);                            \
        pf r1_01=PADD(c1,d1), r1_10=PADD(a1,b1), r1_44=PADD(r1_01,r1_10), r1_s=PADD(a1,d1); \
        pf q2=PADD(a2,d2), q3=PADD(a3,d3);                                         \
        pf r4_01=PADD(c4,d4), r4_10=PADD(a4,b4), r4_44=PADD(r4_01,r4_10), r4_s=PADD(a4,d4); \
        pf t23=PADD(q2,q3);                                                        \
        TERM_R(PADD(PADD(r1_01,d2),PADD(q3,r4_44)), 9)                             \
        TERM_R(PADD(PADD(r1_10,a2),PADD(q3,r4_44)), 9)                             \
        TERM_R(PADD(PADD(r1_44,q2),PADD(d3,r4_01)), 9)                             \
        TERM_R(PADD(PADD(r1_44,q2),PADD(a3,r4_10)), 9)                             \
        TERM_R(PADD(PADD(r1_s,t23),r4_44), 10)                                     \
        TERM_R(PADD(PADD(r1_44,PADD(d2,d3)),r4_44), 10)                            \
        TERM_R(PADD(PADD(r1_44,t23),r4_s), 10)                                     \
        TERM_R(PADD(PADD(r1_44,PADD(a2,a3)),r4_44), 10)                            \
    }                                                                              \
    {   /* K3 (rows/cols 2..4) */                                                  \
        pf a2=RW(2,2),b2=RW(2,3),c2=RW(2,4);                                       \
        pf a3=RW(3,2),c3=RW(3,4);                                                  \
        pf a4=RW(4,2),b4=RW(4,3),c4=RW(4,4);                                       \
        pf r2_10=PADD(a2,b2), r2_33=PADD(r2_10,c2), r2_s=PADD(a2,c2), r2_01=PADD(b2,c2); \
        pf q3=PADD(a3,c3);                                                         \
        pf r4_10=PADD(a4,b4), r4_33=PADD(r4_10,c4), r4_s=PADD(a4,c4), r4_01=PADD(b4,c4); \
        TERM_R(PADD(PADD(r2_33,c3),r4_33), 7)                                      \
        TERM_R(PADD(PADD(r2_33,q3),r4_s), 7)                                       \
        TERM_R(PADD(PADD(r2_33,a3),r4_33), 7)                                      \
        TERM_R(PADD(PADD(r2_s,q3),r4_33), 7)                                       \
        TERM_R(PADD(PADD(r2_01,q3),r4_33), 7)                                      \
        TERM_R(PADD(PADD(r2_33,q3),r4_01), 7)                                      \
        TERM_R(PADD(PADD(r2_33,q3),r4_10), 7)                                      \
        TERM_R(PADD(PADD(r2_10,q3),r4_33), 7)                                      \
    }

// ---------------- init ----------------
__global__ void init_kernel(){
    int t = threadIdx.x;
    if (t < 4) g_tmax[t] = 0;
    if (t < 6) g_vmax[t] = 0;
}

// ---------------- erosion pass A ----------------
__global__ __launch_bounds__(256) void erode_max(const float* __restrict__ psrc,
                                                 const float* __restrict__ gsrc,
                                                 int lvl){
    __shared__ float sW[8], sW2[8];
    const int img = blockIdx.y;
    const float* src;
    if (lvl == 1) src = (img < 8) ? psrc + img*NPIX : gsrc + (img-8)*NPIX;
    else          src = (img < 8) ? g_pe1 + img*NPIX : g_ge1 + (img-8)*NPIX;
    const int tid = threadIdx.x;
    float mt = 0.f, mr = 0.f;
#pragma unroll
    for (int k = 0; k < 4; ++k){
        int idx = blockIdx.x*1024 + k*256 + tid;
        int y = idx >> 9, x = idx & 511;
        float t = 0.f;
        if (y > 0)    t += src[idx - HW];
        if (y < HW-1) t += src[idx + HW];
        if (x > 0)    t += src[idx - 1];
        if (x < HW-1) t += src[idx + 1];
        mt = fmaxf(mt, t);
        if (lvl == 1) mr = fmaxf(mr, src[idx]);
    }
#pragma unroll
    for (int o = 16; o > 0; o >>= 1){
        mt = fmaxf(mt, __shfl_xor_sync(0xffffffffu, mt, o));
        mr = fmaxf(mr, __shfl_xor_sync(0xffffffffu, mr, o));
    }
    if ((tid & 31) == 0){ sW[tid>>5] = mt; sW2[tid>>5] = mr; }
    __syncthreads();
    if (tid == 0){
#pragma unroll
        for (int i = 1; i < 8; ++i){ mt = fmaxf(mt, sW[i]); mr = fmaxf(mr, sW2[i]); }
        atomicMax(&g_tmax[2*(lvl-1) + (img < 8 ? 0 : 1)], __float_as_int(mt));
        if (lvl == 1) atomicMax(&g_vmax[img < 8 ? 0 : 3], __float_as_int(mr));
    }
}

// ---------------- erosion pass B ----------------
__global__ __launch_bounds__(256) void erode_finish(const float* __restrict__ psrc,
                                                    const float* __restrict__ gsrc,
                                                    int lvl){
    __shared__ float sW[8];
    const int img = blockIdx.y;
    const float* src;
    float* dst;
    if (lvl == 1){ src = (img < 8) ? psrc + img*NPIX : gsrc + (img-8)*NPIX;
                   dst = (img < 8) ? g_pe1 + img*NPIX : g_ge1 + (img-8)*NPIX; }
    else         { src = (img < 8) ? g_pe1 + img*NPIX : g_ge1 + (img-8)*NPIX;
                   dst = (img < 8) ? g_pe2 + img*NPIX : g_ge2 + (img-8)*NPIX; }
    const int tid = threadIdx.x;
    const float tmax = __int_as_float(g_tmax[2*(lvl-1) + (img < 8 ? 0 : 1)]);
    float mv = 0.f;
#pragma unroll
    for (int k = 0; k < 4; ++k){
        int idx = blockIdx.x*1024 + k*256 + tid;
        int y = idx >> 9, x = idx & 511;
        float t = 0.f;
        if (y > 0)    t += src[idx - HW];
        if (y < HW-1) t += src[idx + HW];
        if (x > 0)    t += src[idx - 1];
        if (x < HW-1) t += src[idx + 1];
        float v = sigm(10.f * (t / (tmax + 1e-8f) - 0.7f));
        dst[idx] = v;
        mv = fmaxf(mv, v);
    }
#pragma unroll
    for (int o = 16; o > 0; o >>= 1) mv = fmaxf(mv, __shfl_xor_sync(0xffffffffu, mv, o));
    if ((tid & 31) == 0) sW[tid >> 5] = mv;
    __syncthreads();
    if (tid == 0){
#pragma unroll
        for (int i = 1; i < 8; ++i) mv = fmaxf(mv, sW[i]);
        atomicMax(&g_vmax[(img < 8 ? 0 : 3) + lvl], __float_as_int(mv));
    }
}

// ---------------- interior: merged inv0+inv1 ----------------
// grid (14,14,24): tile (bx+1, by+1); z = level*8 + b
__global__ __launch_bounds__(NT) void cp_int_kernel(const float* __restrict__ pred0,
                                                    const float* __restrict__ gt0){
    __shared__ pf    fA[39*PK];
    __shared__ pf    fB[39*PK];
    __shared__ float sS[2][SSN*SSP];
    __shared__ float sR[NT];
    const int tid = threadIdx.x;
    const int level = blockIdx.z >> 3;
    const int b     = blockIdx.z & 7;
    const int oy = (blockIdx.y + 1) * TS, ox = (blockIdx.x + 1) * TS;
    const pf NL2E = PK2(-L2E, -L2E);
    const pf NEG1 = PK2(-1.f, -1.f);

    float cp[2][2][4];
    for (int ts = 0; ts < 2; ++ts){
        const float* base = (ts == 0)
            ? (level == 0 ? pred0 : (level == 1 ? g_pe1 : g_pe2))
            : (level == 0 ? gt0   : (level == 1 ? g_ge1 : g_ge2));
        const float* src = base + b*NPIX;
        const float vmax = __int_as_float(g_vmax[(ts ? 3 : 0) + level]);
        const float kv = vmax * L2E;
        // Ck = k*vmax*L2E - L2E, packed, for k in {7,9,10,11,13,16}
        const pf C7  = PK2(7.f*kv - L2E,  7.f*kv - L2E);
        const pf C9  = PK2(9.f*kv - L2E,  9.f*kv - L2E);
        const pf C10 = PK2(10.f*kv - L2E, 10.f*kv - L2E);
        const pf C11 = PK2(11.f*kv - L2E, 11.f*kv - L2E);
        const pf C13 = PK2(13.f*kv - L2E, 13.f*kv - L2E);
        const pf C16 = PK2(16.f*kv - L2E, 16.f*kv - L2E);

        // Load tile scaled by L2E (fully interior: no pad logic).
        float* A = (float*)fA; float* B = (float*)fB;
        for (int i = tid; i < 39*39; i += NT){
            int a = i / 39, c = i - a*39;
            float v = src[(oy - 4 + a)*HW + (ox - 4 + c)] * L2E;
            A[(c*PK + (a >> 1))*2 + (a & 1)] = v;
            if (a & 1)       B[(c*PK + (a >> 1))*2]         = v;
            else if (a >= 2) B[(c*PK + (a >> 1) - 1)*2 + 1] = v;
        }
        __syncthreads();

        for (int idx = tid; idx < 34*17; idx += NT){
            int p = idx / 34, x = idx - p*34;
#define RW(r,c) ( ((r) & 1) ? fB[(x+(c))*PK + p + ((r)>>1)] : fA[(x+(c))*PK + p + ((r)>>1)] )
#define CSEL(k) ((k)==7?C7:(k)==9?C9:(k)==10?C10:(k)==11?C11:(k)==13?C13:C16)
#define TERM_N(e,k) { pf _w=(e); side_nr (PADD(_w,NL2E), Sn); side_nr (PFMA(_w,NEG1,CSEL(k)), Si); }
#define TERM_R(e,k) { pf _w=(e); side_rcp(PADD(_w,NL2E), Sn); side_rcp(PFMA(_w,NEG1,CSEL(k)), Si); }
            pf Sn = 0ull, Si = 0ull;
            TREE_BODY
            float S0n,S1n,S0i,S1i; UPK(Sn,S0n,S1n); UPK(Si,S0i,S1i);
            float w0,w1; UPK(RW(3,3), w0, w1);
#undef TERM_N
#undef TERM_R
#undef CSEL
#undef RW
            float c00 = w0 * IL2E, c01 = w1 * IL2E;
            int sy = 2*p;
            sS[0][sy*SSP + x]     = sigm(10.f*(c00*S0n - 0.5f));
            sS[0][(sy+1)*SSP + x] = sigm(10.f*(c01*S1n - 0.5f));
            sS[1][sy*SSP + x]     = sigm(10.f*((vmax - c00)*S0i - 0.5f));
            sS[1][(sy+1)*SSP + x] = sigm(10.f*((vmax - c01)*S1i - 0.5f));
        }
        __syncthreads();

#pragma unroll
        for (int v = 0; v < 2; ++v)
#pragma unroll
        for (int q = 0; q < 4; ++q){
            int ly = (tid >> 5) + q*8, lx = tid & 31;
            float acc = 0.f;
#pragma unroll
            for (int dy = 0; dy < 3; ++dy)
#pragma unroll
                for (int dx = 0; dx < 3; ++dx)
                    acc += sS[v][(ly+dy)*SSP + lx + dx];
            cp[ts][v][q] = fminf(fmaxf(acc, 0.f), 1.f);
        }
        __syncthreads();
    }

    float local = 0.f;
#pragma unroll
    for (int v = 0; v < 2; ++v)
#pragma unroll
    for (int q = 0; q < 4; ++q){
        float d = cp[0][v][q] - cp[1][v][q];
        local += d*d;
    }
    sR[tid] = local; __syncthreads();
    for (int o = NT/2; o > 0; o >>= 1){
        if (tid < o) sR[tid] += sR[tid+o];
        __syncthreads();
    }
    if (tid == 0)
        g_partial[(blockIdx.z*196) + blockIdx.y*14 + blockIdx.x] = sR[0];
}

// ---------------- boundary: general path (60 edge tiles) ----------------
// grid (60,1,48): z = (level*2+inv)*8 + b
__global__ __launch_bounds__(NT) void cp_edge_kernel(const float* __restrict__ pred0,
                                                     const float* __restrict__ gt0){
    __shared__ pf    fA[39*PK];
    __shared__ pf    fB[39*PK];
    __shared__ float sS[SSN*SSP];
    __shared__ float sR[NT];
    const int tid = threadIdx.x;
    const int pt  = blockIdx.z >> 3;
    const int b   = blockIdx.z & 7;
    const int level = pt >> 1;
    const int inv   = pt & 1;
    int t = blockIdx.x, bx, by;
    if      (t < 16){ bx = t;      by = 0;      }
    else if (t < 32){ bx = t - 16; by = 15;     }
    else if (t < 46){ bx = 0;      by = t - 31; }
    else            { bx = 15;     by = t - 45; }
    const int oy = by * TS, ox = bx * TS;
    const pf NL2E = PK2(-L2E, -L2E);

    float cp[2][4];
    for (int ts = 0; ts < 2; ++ts){
        const float* base = (ts == 0)
            ? (level == 0 ? pred0 : (level == 1 ? g_pe1 : g_pe2))
            : (level == 0 ? gt0   : (level == 1 ? g_ge1 : g_ge2));
        const float* src = base + b*NPIX;
        float vmax = inv ? __int_as_float(g_vmax[(ts ? 3 : 0) + level]) : 0.f;

        float* A = (float*)fA; float* B = (float*)fB;
        for (int i = tid; i < 39*39; i += NT){
            int a = i / 39, c = i - a*39;
            int qy = oy - 4 + a, qx = ox - 4 + c;
            float v;
            if (qy < -1 || qy > HW || qx < -1 || qx > HW) v = 0.f;
            else if (qy == -1 || qy == HW || qx == -1 || qx == HW) v = L2E;
            else { float u = src[qy*HW + qx]; v = (inv ? vmax - u : u) * L2E; }
            A[(c*PK + (a >> 1))*2 + (a & 1)] = v;
            if (a & 1)       B[(c*PK + (a >> 1))*2]         = v;
            else if (a >= 2) B[(c*PK + (a >> 1) - 1)*2 + 1] = v;
        }
        __syncthreads();

        for (int idx = tid; idx < 34*17; idx += NT){
            int p = idx / 34, x = idx - p*34;
#define RW(r,c) ( ((r) & 1) ? fB[(x+(c))*PK + p + ((r)>>1)] : fA[(x+(c))*PK + p + ((r)>>1)] )
#define TERM_N(e,k) { side_nr (PADD((e),NL2E), Sn); }
#define TERM_R(e,k) { side_rcp(PADD((e),NL2E), Sn); }
            pf Sn = 0ull;
            TREE_BODY
            float S0,S1; UPK(Sn,S0,S1);
            float w0,w1; UPK(RW(3,3), w0, w1);
#undef TERM_N
#undef TERM_R
#undef RW
            float c00 = w0 * IL2E, c01 = w1 * IL2E;
            int sy = 2*p;
            int gy0 = oy + sy - 1, gx = ox + x - 1;
            float s0 = sigm(10.f*(c00*S0 - 0.5f));
            float s1 = sigm(10.f*(c01*S1 - 0.5f));
            bool okx = ((unsigned)gx < HW);
            if (!okx || (unsigned)gy0     >= HW) s0 = 0.f;
            if (!okx || (unsigned)(gy0+1) >= HW) s1 = 0.f;
            sS[sy*SSP + x]     = s0;
            sS[(sy+1)*SSP + x] = s1;
        }
        __syncthreads();

#pragma unroll
        for (int q = 0; q < 4; ++q){
            int ly = (tid >> 5) + q*8, lx = tid & 31;
            float acc = 0.f;
#pragma unroll
            for (int dy = 0; dy < 3; ++dy)
#pragma unroll
                for (int dx = 0; dx < 3; ++dx)
                    acc += sS[(ly+dy)*SSP + lx + dx];
            cp[ts][q] = fminf(fmaxf(acc, 0.f), 1.f);
        }
        __syncthreads();
    }

    float local = 0.f;
#pragma unroll
    for (int q = 0; q < 4; ++q){
        float d = cp[0][q] - cp[1][q];
        local += d*d;
    }
    sR[tid] = local; __syncthreads();
    for (int o = NT/2; o > 0; o >>= 1){
        if (tid < o) sR[tid] += sR[tid+o];
        __syncthreads();
    }
    if (tid == 0)
        g_partial[4704 + blockIdx.z*60 + blockIdx.x] = sR[0];
}

// ---------------- deterministic final reduction ----------------
__global__ __launch_bounds__(256) void final_kernel(float* out){
    __shared__ double sh[256];
    double a = 0.0;
    for (int i = threadIdx.x; i < 7584; i += 256) a += (double)g_partial[i];
    sh[threadIdx.x] = a; __syncthreads();
    for (int o = 128; o > 0; o >>= 1){
        if (threadIdx.x < o) sh[threadIdx.x] += sh[threadIdx.x+o];
        __syncthreads();
    }
    if (threadIdx.x == 0) out[0] = (float)(sh[0] * 0.125);
}

// ---------------- launch ----------------
extern "C" void kernel_launch(void* const* d_in, const int* in_sizes, int n_in,
                              void* d_out, int out_size){
    const float* pred = (const float*)d_in[0];
    const float* gt   = (const float*)d_in[1];
    float* out = (float*)d_out;
    (void)in_sizes; (void)n_in; (void)out_size;

    init_kernel<<<1, 32>>>();
    erode_max   <<<dim3(256, 16), 256>>>(pred, gt, 1);
    erode_finish<<<dim3(256, 16), 256>>>(pred, gt, 1);
    erode_max   <<<dim3(256, 16), 256>>>(pred, gt, 2);
    erode_finish<<<dim3(256, 16), 256>>>(pred, gt, 2);
    cp_int_kernel <<<dim3(14, 14, 24), NT>>>(pred, gt);
    cp_edge_kernel<<<dim3(60, 1, 48), NT>>>(pred, gt);
    final_kernel<<<1, 256>>>(out);
}

// round 7
// speedup vs baseline: 1.8326x; 1.1458x over previous
#include <cuda_runtime.h>

#define HW   512
#define NPIX (512*512)

// ---------------- scratch ----------------
__device__ float g_pe1[8*NPIX], g_pe2[8*NPIX];
__device__ float g_ge1[8*NPIX], g_ge2[8*NPIX];
__device__ int   g_tmax[4];
__device__ int   g_vmax[6];
__device__ float g_partial[7680];

#define L2E   14.4269504f    // 10*log2(e)
#define HL2E  7.2134752f     // L2E/2
#define IL2E  0.069314718f
#define MCL   1048576.f      // 2^20 clamp on m (n-side): e <= 2^40

__device__ __forceinline__ float ex2a(float x){ float r; asm("ex2.approx.ftz.f32 %0, %1;" : "=f"(r) : "f"(x)); return r; }
__device__ __forceinline__ float rcpa(float x){ float r; asm("rcp.approx.ftz.f32 %0, %1;" : "=f"(r) : "f"(x)); return r; }
__device__ __forceinline__ float sigm(float z){ return __fdividef(1.0f, 1.0f + __expf(-z)); }

typedef unsigned long long pf;
__device__ __forceinline__ pf PADD(pf a, pf b){ pf r; asm("add.rn.f32x2 %0, %1, %2;" : "=l"(r) : "l"(a), "l"(b)); return r; }
__device__ __forceinline__ pf PMUL(pf a, pf b){ pf r; asm("mul.rn.f32x2 %0, %1, %2;" : "=l"(r) : "l"(a), "l"(b)); return r; }
__device__ __forceinline__ pf PFMA(pf a, pf b, pf c){ pf r; asm("fma.rn.f32x2 %0, %1, %2, %3;" : "=l"(r) : "l"(a), "l"(b), "l"(c)); return r; }
__device__ __forceinline__ pf PK2(float lo, float hi){ pf r; asm("mov.b64 %0, {%1, %2};" : "=l"(r) : "f"(lo), "f"(hi)); return r; }
__device__ __forceinline__ void UPK(pf a, float& lo, float& hi){ asm("mov.b64 {%0, %1}, %2;" : "=f"(lo), "=f"(hi) : "l"(a)); }

#define C_ONE2  PK2(1.f,1.f)
#define C_TWO2  PK2(2.f,2.f)
#define C_HALF2 PK2(0.5f,0.5f)
#define C_NH2   PK2(-HL2E,-HL2E)

// ---- shared exponent: m = 2^{(w - L2E)/2} for both sites of a packed value ----
__device__ __forceinline__ void mexp(pf w2, pf& m2, pf& mn2){
    pf u2 = PFMA(w2, C_HALF2, C_NH2);
    float u0,u1; UPK(u2,u0,u1);
    float m0 = ex2a(u0), m1 = ex2a(u1);
    m2  = PK2(m0, m1);
    mn2 = PK2(fminf(m0,MCL), fminf(m1,MCL));
}
// n-side pair: Sn += 1/(1+mA^2) + 1/(1+mB^2)
__device__ __forceinline__ void npair(pf mnA, pf mnB, pf& Sn){
    pf eA = PMUL(mnA,mnA), eB = PMUL(mnB,mnB);
    pf s  = PADD(eA,eB);
    pf d  = PFMA(eA, eB, PADD(C_ONE2, s));
    pf n  = PADD(C_TWO2, s);
    float d0,d1; UPK(d,d0,d1);
    Sn = PFMA(n, PK2(rcpa(d0),rcpa(d1)), Sn);
}
// inv-side pair: Si += a/(a+1)+b/(b+1), a=(mA*ih)^2, b=(mB*ih)^2
__device__ __forceinline__ void ipair(pf mA, pf mB, pf ih, pf& Si){
    pf qA = PMUL(mA, ih), qB = PMUL(mB, ih);
    pf a  = PMUL(qA,qA),  b  = PMUL(qB,qB);
    pf s  = PADD(a,b);
    pf p  = PMUL(a,b);
    pf d  = PADD(PADD(C_ONE2,s), p);
    pf n  = PFMA(p, C_TWO2, s);
    float d0,d1; UPK(d,d0,d1);
    Si = PFMA(n, PK2(rcpa(d0),rcpa(d1)), Si);
}
// singles
__device__ __forceinline__ void nsingle(pf mn, pf& Sn){
    pf e = PMUL(mn,mn);
    pf d = PADD(C_ONE2, e);
    float d0,d1; UPK(d,d0,d1);
    Sn = PADD(Sn, PK2(rcpa(d0),rcpa(d1)));
}
__device__ __forceinline__ void isingle(pf m, pf ih, pf& Si){
    pf q = PMUL(m, ih);
    pf a = PMUL(q,q);
    pf d = PADD(C_ONE2, a);
    float d0,d1; UPK(d,d0,d1);
    Si = PFMA(a, PK2(rcpa(d0),rcpa(d1)), Si);
}

// ---------------- geometry ----------------
#define SSN 34
#define SSP 35
#define NT  256
#define TS  32
#define PK  21

// Paired 31-mask tree. Caller defines RW(r,c), TERMP(eA,eB,k), TERMS(e,k).
#define TREE_BODY2                                                                 \
    {   /* K6 */                                                                   \
        pf a0=RW(0,0),b0=RW(0,1),c0_=RW(0,2),d0=RW(0,3),e0=RW(0,4),f0=RW(0,5);     \
        pf a1=RW(1,0),f1=RW(1,5);                                                  \
        pf a2=RW(2,0),f2=RW(2,5);                                                  \
        pf a3=RW(3,0),f3=RW(3,5);                                                  \
        pf a4=RW(4,0),f4=RW(4,5);                                                  \
        pf a5=RW(5,0),b5=RW(5,1),c5=RW(5,2),d5=RW(5,3),e5=RW(5,4),f5=RW(5,5);      \
        pf r0_03=PADD(e0,f0), r0_30=PADD(a0,b0);                                   \
        pf r0_66=PADD(PADD(r0_30,PADD(c0_,d0)),r0_03);                             \
        pf r5_03=PADD(e5,f5), r5_30=PADD(a5,b5);                                   \
        pf r5_66=PADD(PADD(r5_30,PADD(c5,d5)),r5_03), r5_s=PADD(a5,f5);            \
        pf r1_s=PADD(a1,f1), r2_s=PADD(a2,f2), r3_s=PADD(a3,f3), r4_s=PADD(a4,f4); \
        pf t23a=PADD(a2,a3), t123a=PADD(a1,t23a), t234a=PADD(t23a,a4);             \
        pf t23f=PADD(f2,f3), t123f=PADD(f1,t23f), t234f=PADD(t23f,f4);             \
        TERMP(PADD(PADD(r0_03,t123f),PADD(r4_s,r5_66)),                            \
              PADD(PADD(r0_30,t123a),PADD(r4_s,r5_66)), 13)                        \
        TERMP(PADD(PADD(r0_66,r1_s),PADD(t234a,r5_30)),                            \
              PADD(PADD(r0_66,r1_s),PADD(t234f,r5_03)), 13)                        \
        TERMP(PADD(PADD(r0_66,t123a),PADD(a4,r5_66)),                              \
              PADD(PADD(r0_66,t123f),PADD(f4,r5_66)), 16)                          \
        TERMS(PADD(PADD(r0_66,PADD(r1_s,r2_s)),PADD(PADD(r3_s,r4_s),r5_s)), 16)    \
    }                                                                              \
    {   /* K5 */                                                                   \
        pf a1=RW(1,1),b1=RW(1,2),c1=RW(1,3),d1=RW(1,4),e1=RW(1,5);                 \
        pf a2=RW(2,1),e2=RW(2,5);                                                  \
        pf a3=RW(3,1),e3=RW(3,5);                                                  \
        pf a4=RW(4,1),e4=RW(4,5);                                                  \
        pf a5=RW(5,1),b5=RW(5,2),c5=RW(5,3),d5=RW(5,4),e5=RW(5,5);                 \
        pf r1_02=PADD(d1,e1), r1_20=PADD(a1,b1);                                   \
        pf r1_55=PADD(PADD(r1_20,c1),r1_02), r1_s=PADD(a1,e1);                     \
        pf q2=PADD(a2,e2), q3=PADD(a3,e3), q4=PADD(a4,e4);                         \
        pf r5_02=PADD(d5,e5), r5_20=PADD(a5,b5);                                   \
        pf r5_55=PADD(PADD(r5_20,c5),r5_02), r5_s=PADD(a5,e5);                     \
        pf t23a=PADD(a2,a3), t23e=PADD(e2,e3), t234=PADD(PADD(q2,q3),q4);          \
        TERMP(PADD(PADD(r1_02,t23e),PADD(q4,r5_55)),                               \
              PADD(PADD(r1_20,t23a),PADD(q4,r5_55)), 11)                           \
        TERMP(PADD(PADD(r1_55,q2),PADD(PADD(a3,a4),r5_20)),                        \
              PADD(PADD(r1_55,q2),PADD(PADD(e3,e4),r5_02)), 11)                    \
        TERMP(PADD(PADD(r1_55,t23a),PADD(a4,r5_55)),                               \
              PADD(PADD(r1_55,t23e),PADD(e4,r5_55)), 13)                           \
        TERMP(PADD(PADD(r1_55,t234),r5_s),                                         \
              PADD(PADD(r1_s,t234),r5_55), 13)                                     \
    }                                                                              \
    {   /* K4 */                                                                   \
        pf a1=RW(1,1),b1=RW(1,2),c1=RW(1,3),d1=RW(1,4);                            \
        pf a2=RW(2,1),d2=RW(2,4);                                                  \
        pf a3=RW(3,1),d3=RW(3,4);                                                  \
        pf a4=RW(4,1),b4=RW(4,2),c4=RW(4,3),d4=RW(4,4);                            \
        pf r1_01=PADD(c1,d1), r1_10=PADD(a1,b1), r1_44=PADD(r1_01,r1_10), r1_s=PADD(a1,d1); \
        pf q2=PADD(a2,d2), q3=PADD(a3,d3);                                         \
        pf r4_01=PADD(c4,d4), r4_10=PADD(a4,b4), r4_44=PADD(r4_01,r4_10), r4_s=PADD(a4,d4); \
        pf t23=PADD(q2,q3);                                                        \
        TERMP(PADD(PADD(r1_01,d2),PADD(q3,r4_44)),                                 \
              PADD(PADD(r1_10,a2),PADD(q3,r4_44)), 9)                              \
        TERMP(PADD(PADD(r1_44,q2),PADD(d3,r4_01)),                                 \
              PADD(PADD(r1_44,q2),PADD(a3,r4_10)), 9)                              \
        TERMP(PADD(PADD(r1_s,t23),r4_44),                                          \
              PADD(PADD(r1_44,PADD(d2,d3)),r4_44), 10)                             \
        TERMP(PADD(PADD(r1_44,t23),r4_s),                                          \
              PADD(PADD(r1_44,PADD(a2,a3)),r4_44), 10)                             \
    }                                                                              \
    {   /* K3 */                                                                   \
        pf a2=RW(2,2),b2=RW(2,3),c2=RW(2,4);                                       \
        pf a3=RW(3,2),c3=RW(3,4);                                                  \
        pf a4=RW(4,2),b4=RW(4,3),c4=RW(4,4);                                       \
        pf r2_10=PADD(a2,b2), r2_33=PADD(r2_10,c2), r2_s=PADD(a2,c2), r2_01=PADD(b2,c2); \
        pf q3=PADD(a3,c3);                                                         \
        pf r4_10=PADD(a4,b4), r4_33=PADD(r4_10,c4), r4_s=PADD(a4,c4), r4_01=PADD(b4,c4); \
        TERMP(PADD(PADD(r2_33,c3),r4_33), PADD(PADD(r2_33,q3),r4_s), 7)            \
        TERMP(PADD(PADD(r2_33,a3),r4_33), PADD(PADD(r2_s,q3),r4_33), 7)            \
        TERMP(PADD(PADD(r2_01,q3),r4_33), PADD(PADD(r2_33,q3),r4_01), 7)           \
        TERMP(PADD(PADD(r2_33,q3),r4_10), PADD(PADD(r2_10,q3),r4_33), 7)           \
    }

// ---------------- init ----------------
__global__ void init_kernel(){
    int t = threadIdx.x;
    if (t < 4) g_tmax[t] = 0;
    if (t < 6) g_vmax[t] = 0;
}

// ---------------- erosion pass A ----------------
__global__ __launch_bounds__(256) void erode_max(const float* __restrict__ psrc,
                                                 const float* __restrict__ gsrc,
                                                 int lvl){
    __shared__ float sW[8], sW2[8];
    const int img = blockIdx.y;
    const float* src;
    if (lvl == 1) src = (img < 8) ? psrc + img*NPIX : gsrc + (img-8)*NPIX;
    else          src = (img < 8) ? g_pe1 + img*NPIX : g_ge1 + (img-8)*NPIX;
    const int tid = threadIdx.x;
    float mt = 0.f, mr = 0.f;
#pragma unroll
    for (int k = 0; k < 4; ++k){
        int idx = blockIdx.x*1024 + k*256 + tid;
        int y = idx >> 9, x = idx & 511;
        float t = 0.f;
        if (y > 0)    t += src[idx - HW];
        if (y < HW-1) t += src[idx + HW];
        if (x > 0)    t += src[idx - 1];
        if (x < HW-1) t += src[idx + 1];
        mt = fmaxf(mt, t);
        if (lvl == 1) mr = fmaxf(mr, src[idx]);
    }
#pragma unroll
    for (int o = 16; o > 0; o >>= 1){
        mt = fmaxf(mt, __shfl_xor_sync(0xffffffffu, mt, o));
        mr = fmaxf(mr, __shfl_xor_sync(0xffffffffu, mr, o));
    }
    if ((tid & 31) == 0){ sW[tid>>5] = mt; sW2[tid>>5] = mr; }
    __syncthreads();
    if (tid == 0){
#pragma unroll
        for (int i = 1; i < 8; ++i){ mt = fmaxf(mt, sW[i]); mr = fmaxf(mr, sW2[i]); }
        atomicMax(&g_tmax[2*(lvl-1) + (img < 8 ? 0 : 1)], __float_as_int(mt));
        if (lvl == 1) atomicMax(&g_vmax[img < 8 ? 0 : 3], __float_as_int(mr));
    }
}

// ---------------- erosion pass B ----------------
__global__ __launch_bounds__(256) void erode_finish(const float* __restrict__ psrc,
                                                    const float* __restrict__ gsrc,
                                                    int lvl){
    __shared__ float sW[8];
    const int img = blockIdx.y;
    const float* src;
    float* dst;
    if (lvl == 1){ src = (img < 8) ? psrc + img*NPIX : gsrc + (img-8)*NPIX;
                   dst = (img < 8) ? g_pe1 + img*NPIX : g_ge1 + (img-8)*NPIX; }
    else         { src = (img < 8) ? g_pe1 + img*NPIX : g_ge1 + (img-8)*NPIX;
                   dst = (img < 8) ? g_pe2 + img*NPIX : g_ge2 + (img-8)*NPIX; }
    const int tid = threadIdx.x;
    const float tmax = __int_as_float(g_tmax[2*(lvl-1) + (img < 8 ? 0 : 1)]);
    float mv = 0.f;
#pragma unroll
    for (int k = 0; k < 4; ++k){
        int idx = blockIdx.x*1024 + k*256 + tid;
        int y = idx >> 9, x = idx & 511;
        float t = 0.f;
        if (y > 0)    t += src[idx - HW];
        if (y < HW-1) t += src[idx + HW];
        if (x > 0)    t += src[idx - 1];
        if (x < HW-1) t += src[idx + 1];
        float v = sigm(10.f * (t / (tmax + 1e-8f) - 0.7f));
        dst[idx] = v;
        mv = fmaxf(mv, v);
    }
#pragma unroll
    for (int o = 16; o > 0; o >>= 1) mv = fmaxf(mv, __shfl_xor_sync(0xffffffffu, mv, o));
    if ((tid & 31) == 0) sW[tid >> 5] = mv;
    __syncthreads();
    if (tid == 0){
#pragma unroll
        for (int i = 1; i < 8; ++i) mv = fmaxf(mv, sW[i]);
        atomicMax(&g_vmax[(img < 8 ? 0 : 3) + lvl], __float_as_int(mv));
    }
}

// ---------------- interior: merged inv0+inv1, shared exponentials ----------------
__global__ __launch_bounds__(NT) void cp_int_kernel(const float* __restrict__ pred0,
                                                    const float* __restrict__ gt0){
    __shared__ pf    fA[39*PK];
    __shared__ pf    fB[39*PK];
    __shared__ float sS[2][SSN*SSP];
    __shared__ float sR[NT];
    const int tid = threadIdx.x;
    const int level = blockIdx.z >> 3;
    const int b     = blockIdx.z & 7;
    const int oy = (blockIdx.y + 1) * TS, ox = (blockIdx.x + 1) * TS;

    float cp[2][2][4];
    for (int ts = 0; ts < 2; ++ts){
        const float* base = (ts == 0)
            ? (level == 0 ? pred0 : (level == 1 ? g_pe1 : g_pe2))
            : (level == 0 ? gt0   : (level == 1 ? g_ge1 : g_ge2));
        const float* src = base + b*NPIX;
        const float vmax = __int_as_float(g_vmax[(ts ? 3 : 0) + level]);
        // ih_k = 2^{-D_k/2}, D_k = L2E*(k*vmax - 2)
        const float vk = HL2E * vmax;
        const float ih7f  = exp2f(L2E - 7.f*vk);
        const float ih9f  = exp2f(L2E - 9.f*vk);
        const float ih10f = exp2f(L2E - 10.f*vk);
        const float ih11f = exp2f(L2E - 11.f*vk);
        const float ih13f = exp2f(L2E - 13.f*vk);
        const float ih16f = exp2f(L2E - 16.f*vk);
        const pf IH7  = PK2(ih7f,ih7f),   IH9  = PK2(ih9f,ih9f);
        const pf IH10 = PK2(ih10f,ih10f), IH11 = PK2(ih11f,ih11f);
        const pf IH13 = PK2(ih13f,ih13f), IH16 = PK2(ih16f,ih16f);

        float* A = (float*)fA; float* B = (float*)fB;
        for (int i = tid; i < 39*39; i += NT){
            int a = i / 39, c = i - a*39;
            float v = src[(oy - 4 + a)*HW + (ox - 4 + c)] * L2E;
            A[(c*PK + (a >> 1))*2 + (a & 1)] = v;
            if (a & 1)       B[(c*PK + (a >> 1))*2]         = v;
            else if (a >= 2) B[(c*PK + (a >> 1) - 1)*2 + 1] = v;
        }
        __syncthreads();

        for (int idx = tid; idx < 34*17; idx += NT){
            int p = idx / 34, x = idx - p*34;
#define RW(r,c) ( ((r) & 1) ? fB[(x+(c))*PK + p + ((r)>>1)] : fA[(x+(c))*PK + p + ((r)>>1)] )
#define TERMP(eA,eB,k) { pf mA,mnA,mB,mnB; mexp((eA),mA,mnA); mexp((eB),mB,mnB); \
                         npair(mnA,mnB,Sn); ipair(mA,mB,IH##k,Si); }
#define TERMS(e,k)     { pf m,mn; mexp((e),m,mn); nsingle(mn,Sn); isingle(m,IH##k,Si); }
            pf Sn = 0ull, Si = 0ull;
            TREE_BODY2
            float S0n,S1n,S0i,S1i; UPK(Sn,S0n,S1n); UPK(Si,S0i,S1i);
            float w0,w1; UPK(RW(3,3), w0, w1);
#undef TERMP
#undef TERMS
#undef RW
            float c00 = w0 * IL2E, c01 = w1 * IL2E;
            int sy = 2*p;
            sS[0][sy*SSP + x]     = sigm(10.f*(c00*S0n - 0.5f));
            sS[0][(sy+1)*SSP + x] = sigm(10.f*(c01*S1n - 0.5f));
            sS[1][sy*SSP + x]     = sigm(10.f*((vmax - c00)*S0i - 0.5f));
            sS[1][(sy+1)*SSP + x] = sigm(10.f*((vmax - c01)*S1i - 0.5f));
        }
        __syncthreads();

#pragma unroll
        for (int v = 0; v < 2; ++v)
#pragma unroll
        for (int q = 0; q < 4; ++q){
            int ly = (tid >> 5) + q*8, lx = tid & 31;
            float acc = 0.f;
#pragma unroll
            for (int dy = 0; dy < 3; ++dy)
#pragma unroll
                for (int dx = 0; dx < 3; ++dx)
                    acc += sS[v][(ly+dy)*SSP + lx + dx];
            cp[ts][v][q] = fminf(fmaxf(acc, 0.f), 1.f);
        }
        __syncthreads();
    }

    float local = 0.f;
#pragma unroll
    for (int v = 0; v < 2; ++v)
#pragma unroll
    for (int q = 0; q < 4; ++q){
        float d = cp[0][v][q] - cp[1][v][q];
        local += d*d;
    }
    sR[tid] = local; __syncthreads();
    for (int o = NT/2; o > 0; o >>= 1){
        if (tid < o) sR[tid] += sR[tid+o];
        __syncthreads();
    }
    if (tid == 0)
        g_partial[(blockIdx.z*196) + blockIdx.y*14 + blockIdx.x] = sR[0];
}

// ---------------- boundary: general path ----------------
__global__ __launch_bounds__(NT) void cp_edge_kernel(const float* __restrict__ pred0,
                                                     const float* __restrict__ gt0){
    __shared__ pf    fA[39*PK];
    __shared__ pf    fB[39*PK];
    __shared__ float sS[SSN*SSP];
    __shared__ float sR[NT];
    const int tid = threadIdx.x;
    const int pt  = blockIdx.z >> 3;
    const int b   = blockIdx.z & 7;
    const int level = pt >> 1;
    const int inv   = pt & 1;
    int t = blockIdx.x, bx, by;
    if      (t < 16){ bx = t;      by = 0;      }
    else if (t < 32){ bx = t - 16; by = 15;     }
    else if (t < 46){ bx = 0;      by = t - 31; }
    else            { bx = 15;     by = t - 45; }
    const int oy = by * TS, ox = bx * TS;

    float cp[2][4];
    for (int ts = 0; ts < 2; ++ts){
        const float* base = (ts == 0)
            ? (level == 0 ? pred0 : (level == 1 ? g_pe1 : g_pe2))
            : (level == 0 ? gt0   : (level == 1 ? g_ge1 : g_ge2));
        const float* src = base + b*NPIX;
        float vmax = inv ? __int_as_float(g_vmax[(ts ? 3 : 0) + level]) : 0.f;

        float* A = (float*)fA; float* B = (float*)fB;
        for (int i = tid; i < 39*39; i += NT){
            int a = i / 39, c = i - a*39;
            int qy = oy - 4 + a, qx = ox - 4 + c;
            float v;
            if (qy < -1 || qy > HW || qx < -1 || qx > HW) v = 0.f;
            else if (qy == -1 || qy == HW || qx == -1 || qx == HW) v = L2E;
            else { float u = src[qy*HW + qx]; v = (inv ? vmax - u : u) * L2E; }
            A[(c*PK + (a >> 1))*2 + (a & 1)] = v;
            if (a & 1)       B[(c*PK + (a >> 1))*2]         = v;
            else if (a >= 2) B[(c*PK + (a >> 1) - 1)*2 + 1] = v;
        }
        __syncthreads();

        for (int idx = tid; idx < 34*17; idx += NT){
            int p = idx / 34, x = idx - p*34;
#define RW(r,c) ( ((r) & 1) ? fB[(x+(c))*PK + p + ((r)>>1)] : fA[(x+(c))*PK + p + ((r)>>1)] )
#define TERMP(eA,eB,k) { pf mA,mnA,mB,mnB; mexp((eA),mA,mnA); mexp((eB),mB,mnB); \
                         npair(mnA,mnB,Sn); }
#define TERMS(e,k)     { pf m,mn; mexp((e),m,mn); nsingle(mn,Sn); }
            pf Sn = 0ull;
            TREE_BODY2
            float S0,S1; UPK(Sn,S0,S1);
            float w0,w1; UPK(RW(3,3), w0, w1);
#undef TERMP
#undef TERMS
#undef RW
            float c00 = w0 * IL2E, c01 = w1 * IL2E;
            int sy = 2*p;
            int gy0 = oy + sy - 1, gx = ox + x - 1;
            float s0 = sigm(10.f*(c00*S0 - 0.5f));
            float s1 = sigm(10.f*(c01*S1 - 0.5f));
            bool okx = ((unsigned)gx < HW);
            if (!okx || (unsigned)gy0     >= HW) s0 = 0.f;
            if (!okx || (unsigned)(gy0+1) >= HW) s1 = 0.f;
            sS[sy*SSP + x]     = s0;
            sS[(sy+1)*SSP + x] = s1;
        }
        __syncthreads();

#pragma unroll
        for (int q = 0; q < 4; ++q){
            int ly = (tid >> 5) + q*8, lx = tid & 31;
            float acc = 0.f;
#pragma unroll
            for (int dy = 0; dy < 3; ++dy)
#pragma unroll
                for (int dx = 0; dx < 3; ++dx)
                    acc += sS[(ly+dy)*SSP + lx + dx];
            cp[ts][q] = fminf(fmaxf(acc, 0.f), 1.f);
        }
        __syncthreads();
    }

    float local = 0.f;
#pragma unroll
    for (int q = 0; q < 4; ++q){
        float d = cp[0][q] - cp[1][q];
        local += d*d;
    }
    sR[tid] = local; __syncthreads();
    for (int o = NT/2; o > 0; o >>= 1){
        if (tid < o) sR[tid] += sR[tid+o];
        __syncthreads();
    }
    if (tid == 0)
        g_partial[4704 + blockIdx.z*60 + blockIdx.x] = sR[0];
}

// ---------------- deterministic final reduction ----------------
__global__ __launch_bounds__(256) void final_kernel(float* out){
    __shared__ double sh[256];
    double a = 0.0;
    for (int i = threadIdx.x; i < 7584; i += 256) a += (double)g_partial[i];
    sh[threadIdx.x] = a; __syncthreads();
    for (int o = 128; o > 0; o >>= 1){
        if (threadIdx.x < o) sh[threadIdx.x] += sh[threadIdx.x+o];
        __syncthreads();
    }
    if (threadIdx.x == 0) out[0] = (float)(sh[0] * 0.125);
}

// ---------------- launch ----------------
extern "C" void kernel_launch(void* const* d_in, const int* in_sizes, int n_in,
                              void* d_out, int out_size){
    const float* pred = (const float*)d_in[0];
    const float* gt   = (const float*)d_in[1];
    float* out = (float*)d_out;
    (void)in_sizes; (void)n_in; (void)out_size;

    init_kernel<<<1, 32>>>();
    erode_max   <<<dim3(256, 16), 256>>>(pred, gt, 1);
    erode_finish<<<dim3(256, 16), 256>>>(pred, gt, 1);
    erode_max   <<<dim3(256, 16), 256>>>(pred, gt, 2);
    erode_finish<<<dim3(256, 16), 256>>>(pred, gt, 2);
    cp_int_kernel <<<dim3(14, 14, 24), NT>>>(pred, gt);
    cp_edge_kernel<<<dim3(60, 1, 48), NT>>>(pred, gt);
    final_kernel<<<1, 256>>>(out);
}

// round 8
// speedup vs baseline: 1.9318x; 1.0541x over previous
#include <cuda_runtime.h>

#define HW   512
#define NPIX (512*512)

// ---------------- scratch ----------------
__device__ float g_pe1[8*NPIX], g_pe2[8*NPIX];
__device__ float g_ge1[8*NPIX], g_ge2[8*NPIX];
__device__ int   g_tmax[4];
__device__ int   g_vmax[6];
__device__ float g_partial[7680];

#define L2E   14.4269504f    // 10*log2(e)
#define HL2E  7.2134752f     // L2E/2
#define IL2E  0.069314718f
#define L2E1  1.44269504f    // log2(e)
#define MCL   1048576.f      // 2^20 clamp on m (n-side)

__device__ __forceinline__ float ex2a(float x){ float r; asm("ex2.approx.ftz.f32 %0, %1;" : "=f"(r) : "f"(x)); return r; }
__device__ __forceinline__ float rcpa(float x){ float r; asm("rcp.approx.ftz.f32 %0, %1;" : "=f"(r) : "f"(x)); return r; }
// sigmoid(10*(v - beta)) via ex2/rcp approx
__device__ __forceinline__ float sigm10(float v, float beta){
    return rcpa(1.f + ex2a((beta - v) * L2E));
}

typedef unsigned long long pf;
__device__ __forceinline__ pf PADD(pf a, pf b){ pf r; asm("add.rn.f32x2 %0, %1, %2;" : "=l"(r) : "l"(a), "l"(b)); return r; }
__device__ __forceinline__ pf PMUL(pf a, pf b){ pf r; asm("mul.rn.f32x2 %0, %1, %2;" : "=l"(r) : "l"(a), "l"(b)); return r; }
__device__ __forceinline__ pf PFMA(pf a, pf b, pf c){ pf r; asm("fma.rn.f32x2 %0, %1, %2, %3;" : "=l"(r) : "l"(a), "l"(b), "l"(c)); return r; }
__device__ __forceinline__ pf PK2(float lo, float hi){ pf r; asm("mov.b64 %0, {%1, %2};" : "=l"(r) : "f"(lo), "f"(hi)); return r; }
__device__ __forceinline__ void UPK(pf a, float& lo, float& hi){ asm("mov.b64 {%0, %1}, %2;" : "=f"(lo), "=f"(hi) : "l"(a)); }

#define C_ONE2  PK2(1.f,1.f)
#define C_TWO2  PK2(2.f,2.f)
#define C_HALF2 PK2(0.5f,0.5f)
#define C_NH2   PK2(-HL2E,-HL2E)

// ---- shared exponent: m = 2^{(w - L2E)/2} ----
__device__ __forceinline__ void mexp(pf w2, pf& m2, pf& mn2){
    pf u2 = PFMA(w2, C_HALF2, C_NH2);
    float u0,u1; UPK(u2,u0,u1);
    float m0 = ex2a(u0), m1 = ex2a(u1);
    m2  = PK2(m0, m1);
    mn2 = PK2(fminf(m0,MCL), fminf(m1,MCL));
}
__device__ __forceinline__ void npair(pf mnA, pf mnB, pf& Sn){
    pf eA = PMUL(mnA,mnA), eB = PMUL(mnB,mnB);
    pf s  = PADD(eA,eB);
    pf d  = PFMA(eA, eB, PADD(C_ONE2, s));
    pf n  = PADD(C_TWO2, s);
    float d0,d1; UPK(d,d0,d1);
    Sn = PFMA(n, PK2(rcpa(d0),rcpa(d1)), Sn);
}
__device__ __forceinline__ void ipair(pf mA, pf mB, pf ih, pf& Si){
    pf qA = PMUL(mA, ih), qB = PMUL(mB, ih);
    pf a  = PMUL(qA,qA),  b  = PMUL(qB,qB);
    pf s  = PADD(a,b);
    pf p  = PMUL(a,b);
    pf d  = PADD(PADD(C_ONE2,s), p);
    pf n  = PFMA(p, C_TWO2, s);
    float d0,d1; UPK(d,d0,d1);
    Si = PFMA(n, PK2(rcpa(d0),rcpa(d1)), Si);
}
__device__ __forceinline__ void nsingle(pf mn, pf& Sn){
    pf e = PMUL(mn,mn);
    pf d = PADD(C_ONE2, e);
    float d0,d1; UPK(d,d0,d1);
    Sn = PADD(Sn, PK2(rcpa(d0),rcpa(d1)));
}
__device__ __forceinline__ void isingle(pf m, pf ih, pf& Si){
    pf q = PMUL(m, ih);
    pf a = PMUL(q,q);
    pf d = PADD(C_ONE2, a);
    float d0,d1; UPK(d,d0,d1);
    Si = PFMA(a, PK2(rcpa(d0),rcpa(d1)), Si);
}

// ---------------- geometry ----------------
#define SSN 34
#define SSP 35
#define NT  256
#define TS  32
#define PK  21

#define TREE_BODY2                                                                 \
    {   /* K6 */                                                                   \
        pf a0=RW(0,0),b0=RW(0,1),c0_=RW(0,2),d0=RW(0,3),e0=RW(0,4),f0=RW(0,5);     \
        pf a1=RW(1,0),f1=RW(1,5);                                                  \
        pf a2=RW(2,0),f2=RW(2,5);                                                  \
        pf a3=RW(3,0),f3=RW(3,5);                                                  \
        pf a4=RW(4,0),f4=RW(4,5);                                                  \
        pf a5=RW(5,0),b5=RW(5,1),c5=RW(5,2),d5=RW(5,3),e5=RW(5,4),f5=RW(5,5);      \
        pf r0_03=PADD(e0,f0), r0_30=PADD(a0,b0);                                   \
        pf r0_66=PADD(PADD(r0_30,PADD(c0_,d0)),r0_03);                             \
        pf r5_03=PADD(e5,f5), r5_30=PADD(a5,b5);                                   \
        pf r5_66=PADD(PADD(r5_30,PADD(c5,d5)),r5_03), r5_s=PADD(a5,f5);            \
        pf r1_s=PADD(a1,f1), r2_s=PADD(a2,f2), r3_s=PADD(a3,f3), r4_s=PADD(a4,f4); \
        pf t23a=PADD(a2,a3), t123a=PADD(a1,t23a), t234a=PADD(t23a,a4);             \
        pf t23f=PADD(f2,f3), t123f=PADD(f1,t23f), t234f=PADD(t23f,f4);             \
        TERMP(PADD(PADD(r0_03,t123f),PADD(r4_s,r5_66)),                            \
              PADD(PADD(r0_30,t123a),PADD(r4_s,r5_66)), 13)                        \
        TERMP(PADD(PADD(r0_66,r1_s),PADD(t234a,r5_30)),                            \
              PADD(PADD(r0_66,r1_s),PADD(t234f,r5_03)), 13)                        \
        TERMP(PADD(PADD(r0_66,t123a),PADD(a4,r5_66)),                              \
              PADD(PADD(r0_66,t123f),PADD(f4,r5_66)), 16)                          \
        TERMS(PADD(PADD(r0_66,PADD(r1_s,r2_s)),PADD(PADD(r3_s,r4_s),r5_s)), 16)    \
    }                                                                              \
    {   /* K5 */                                                                   \
        pf a1=RW(1,1),b1=RW(1,2),c1=RW(1,3),d1=RW(1,4),e1=RW(1,5);                 \
        pf a2=RW(2,1),e2=RW(2,5);                                                  \
        pf a3=RW(3,1),e3=RW(3,5);                                                  \
        pf a4=RW(4,1),e4=RW(4,5);                                                  \
        pf a5=RW(5,1),b5=RW(5,2),c5=RW(5,3),d5=RW(5,4),e5=RW(5,5);                 \
        pf r1_02=PADD(d1,e1), r1_20=PADD(a1,b1);                                   \
        pf r1_55=PADD(PADD(r1_20,c1),r1_02), r1_s=PADD(a1,e1);                     \
        pf q2=PADD(a2,e2), q3=PADD(a3,e3), q4=PADD(a4,e4);                         \
        pf r5_02=PADD(d5,e5), r5_20=PADD(a5,b5);                                   \
        pf r5_55=PADD(PADD(r5_20,c5),r5_02), r5_s=PADD(a5,e5);                     \
        pf t23a=PADD(a2,a3), t23e=PADD(e2,e3), t234=PADD(PADD(q2,q3),q4);          \
        TERMP(PADD(PADD(r1_02,t23e),PADD(q4,r5_55)),                               \
              PADD(PADD(r1_20,t23a),PADD(q4,r5_55)), 11)                           \
        TERMP(PADD(PADD(r1_55,q2),PADD(PADD(a3,a4),r5_20)),                        \
              PADD(PADD(r1_55,q2),PADD(PADD(e3,e4),r5_02)), 11)                    \
        TERMP(PADD(PADD(r1_55,t23a),PADD(a4,r5_55)),                               \
              PADD(PADD(r1_55,t23e),PADD(e4,r5_55)), 13)                           \
        TERMP(PADD(PADD(r1_55,t234),r5_s),                                         \
              PADD(PADD(r1_s,t234),r5_55), 13)                                     \
    }                                                                              \
    {   /* K4 */                                                                   \
        pf a1=RW(1,1),b1=RW(1,2),c1=RW(1,3),d1=RW(1,4);                            \
        pf a2=RW(2,1),d2=RW(2,4);                                                  \
        pf a3=RW(3,1),d3=RW(3,4);                                                  \
        pf a4=RW(4,1),b4=RW(4,2),c4=RW(4,3),d4=RW(4,4);                            \
        pf r1_01=PADD(c1,d1), r1_10=PADD(a1,b1), r1_44=PADD(r1_01,r1_10), r1_s=PADD(a1,d1); \
        pf q2=PADD(a2,d2), q3=PADD(a3,d3);                                         \
        pf r4_01=PADD(c4,d4), r4_10=PADD(a4,b4), r4_44=PADD(r4_01,r4_10), r4_s=PADD(a4,d4); \
        pf t23=PADD(q2,q3);                                                        \
        TERMP(PADD(PADD(r1_01,d2),PADD(q3,r4_44)),                                 \
              PADD(PADD(r1_10,a2),PADD(q3,r4_44)), 9)                              \
        TERMP(PADD(PADD(r1_44,q2),PADD(d3,r4_01)),                                 \
              PADD(PADD(r1_44,q2),PADD(a3,r4_10)), 9)                              \
        TERMP(PADD(PADD(r1_s,t23),r4_44),                                          \
              PADD(PADD(r1_44,PADD(d2,d3)),r4_44), 10)                             \
        TERMP(PADD(PADD(r1_44,t23),r4_s),                                          \
              PADD(PADD(r1_44,PADD(a2,a3)),r4_44), 10)                             \
    }                                                                              \
    {   /* K3 */                                                                   \
        pf a2=RW(2,2),b2=RW(2,3),c2=RW(2,4);                                       \
        pf a3=RW(3,2),c3=RW(3,4);                                                  \
        pf a4=RW(4,2),b4=RW(4,3),c4=RW(4,4);                                       \
        pf r2_10=PADD(a2,b2), r2_33=PADD(r2_10,c2), r2_s=PADD(a2,c2), r2_01=PADD(b2,c2); \
        pf q3=PADD(a3,c3);                                                         \
        pf r4_10=PADD(a4,b4), r4_33=PADD(r4_10,c4), r4_s=PADD(a4,c4), r4_01=PADD(b4,c4); \
        TERMP(PADD(PADD(r2_33,c3),r4_33), PADD(PADD(r2_33,q3),r4_s), 7)            \
        TERMP(PADD(PADD(r2_33,a3),r4_33), PADD(PADD(r2_s,q3),r4_33), 7)            \
        TERMP(PADD(PADD(r2_01,q3),r4_33), PADD(PADD(r2_33,q3),r4_01), 7)           \
        TERMP(PADD(PADD(r2_33,q3),r4_10), PADD(PADD(r2_10,q3),r4_33), 7)           \
    }

// ---------------- init ----------------
__global__ void init_kernel(){
    int t = threadIdx.x;
    if (t < 4) g_tmax[t] = 0;
    if (t < 6) g_vmax[t] = 0;
}

// ---------------- erosion pass A: vectorized cross conv + maxes ----------------
// grid (64, 16): each thread does 4 consecutive px; block = 1024 px rows-aligned
__global__ __launch_bounds__(256) void erode_max(const float* __restrict__ psrc,
                                                 const float* __restrict__ gsrc,
                                                 int lvl){
    __shared__ float sW[8], sW2[8];
    const int img = blockIdx.y;
    const float* src;
    if (lvl == 1) src = (img < 8) ? psrc + img*NPIX : gsrc + (img-8)*NPIX;
    else          src = (img < 8) ? g_pe1 + img*NPIX : g_ge1 + (img-8)*NPIX;
    const int tid = threadIdx.x;
    float mt = 0.f, mr = 0.f;
#pragma unroll
    for (int k = 0; k < 4; ++k){
        int base = blockIdx.x*4096 + k*1024 + tid*4;
        int y = base >> 9, x = base & 511;
        float4 mid = *(const float4*)(src + base);
        float4 up  = (y > 0)    ? *(const float4*)(src + base - HW) : make_float4(0,0,0,0);
        float4 dn  = (y < HW-1) ? *(const float4*)(src + base + HW) : make_float4(0,0,0,0);
        float  lf  = (x > 0)    ? src[base - 1] : 0.f;
        float  rt  = (x < 508)  ? src[base + 4] : 0.f;
        float t0 = up.x + dn.x + lf    + mid.y;
        float t1 = up.y + dn.y + mid.x + mid.z;
        float t2 = up.z + dn.z + mid.y + mid.w;
        float t3 = up.w + dn.w + mid.z + rt;
        mt = fmaxf(mt, fmaxf(fmaxf(t0,t1), fmaxf(t2,t3)));
        if (lvl == 1) mr = fmaxf(mr, fmaxf(fmaxf(mid.x,mid.y), fmaxf(mid.z,mid.w)));
    }
#pragma unroll
    for (int o = 16; o > 0; o >>= 1){
        mt = fmaxf(mt, __shfl_xor_sync(0xffffffffu, mt, o));
        mr = fmaxf(mr, __shfl_xor_sync(0xffffffffu, mr, o));
    }
    if ((tid & 31) == 0){ sW[tid>>5] = mt; sW2[tid>>5] = mr; }
    __syncthreads();
    if (tid == 0){
#pragma unroll
        for (int i = 1; i < 8; ++i){ mt = fmaxf(mt, sW[i]); mr = fmaxf(mr, sW2[i]); }
        atomicMax(&g_tmax[2*(lvl-1) + (img < 8 ? 0 : 1)], __float_as_int(mt));
        if (lvl == 1) atomicMax(&g_vmax[img < 8 ? 0 : 3], __float_as_int(mr));
    }
}

// ---------------- erosion pass B: vectorized ----------------
__global__ __launch_bounds__(256) void erode_finish(const float* __restrict__ psrc,
                                                    const float* __restrict__ gsrc,
                                                    int lvl){
    __shared__ float sW[8];
    const int img = blockIdx.y;
    const float* src;
    float* dst;
    if (lvl == 1){ src = (img < 8) ? psrc + img*NPIX : gsrc + (img-8)*NPIX;
                   dst = (img < 8) ? g_pe1 + img*NPIX : g_ge1 + (img-8)*NPIX; }
    else         { src = (img < 8) ? g_pe1 + img*NPIX : g_ge1 + (img-8)*NPIX;
                   dst = (img < 8) ? g_pe2 + img*NPIX : g_ge2 + (img-8)*NPIX; }
    const int tid = threadIdx.x;
    const float tmax = __int_as_float(g_tmax[2*(lvl-1) + (img < 8 ? 0 : 1)]);
    const float inv = __frcp_rn(tmax + 1e-8f);
    float mv = 0.f;
#pragma unroll
    for (int k = 0; k < 4; ++k){
        int base = blockIdx.x*4096 + k*1024 + tid*4;
        int y = base >> 9, x = base & 511;
        float4 mid = *(const float4*)(src + base);
        float4 up  = (y > 0)    ? *(const float4*)(src + base - HW) : make_float4(0,0,0,0);
        float4 dn  = (y < HW-1) ? *(const float4*)(src + base + HW) : make_float4(0,0,0,0);
        float  lf  = (x > 0)    ? src[base - 1] : 0.f;
        float  rt  = (x < 508)  ? src[base + 4] : 0.f;
        float4 v;
        v.x = sigm10((up.x + dn.x + lf    + mid.y) * inv, 0.7f);
        v.y = sigm10((up.y + dn.y + mid.x + mid.z) * inv, 0.7f);
        v.z = sigm10((up.z + dn.z + mid.y + mid.w) * inv, 0.7f);
        v.w = sigm10((up.w + dn.w + mid.z + rt   ) * inv, 0.7f);
        *(float4*)(dst + base) = v;
        mv = fmaxf(mv, fmaxf(fmaxf(v.x,v.y), fmaxf(v.z,v.w)));
    }
#pragma unroll
    for (int o = 16; o > 0; o >>= 1) mv = fmaxf(mv, __shfl_xor_sync(0xffffffffu, mv, o));
    if ((tid & 31) == 0) sW[tid >> 5] = mv;
    __syncthreads();
    if (tid == 0){
#pragma unroll
        for (int i = 1; i < 8; ++i) mv = fmaxf(mv, sW[i]);
        atomicMax(&g_vmax[(img < 8 ? 0 : 3) + lvl], __float_as_int(mv));
    }
}

// ---------------- interior: merged inv0+inv1, shared exponentials ----------------
__global__ __launch_bounds__(NT, 3) void cp_int_kernel(const float* __restrict__ pred0,
                                                       const float* __restrict__ gt0){
    __shared__ pf    fA[39*PK];
    __shared__ pf    fB[39*PK];
    __shared__ float sS[2][SSN*SSP];
    __shared__ float sR[NT];
    const int tid = threadIdx.x;
    const int level = blockIdx.z >> 3;
    const int b     = blockIdx.z & 7;
    const int oy = (blockIdx.y + 1) * TS, ox = (blockIdx.x + 1) * TS;

    float cp[2][2][4];
    for (int ts = 0; ts < 2; ++ts){
        const float* base = (ts == 0)
            ? (level == 0 ? pred0 : (level == 1 ? g_pe1 : g_pe2))
            : (level == 0 ? gt0   : (level == 1 ? g_ge1 : g_ge2));
        const float* src = base + b*NPIX;
        const float vmax = __int_as_float(g_vmax[(ts ? 3 : 0) + level]);
        const float vk = HL2E * vmax;
        const float ih7f  = exp2f(L2E - 7.f*vk);
        const float ih9f  = exp2f(L2E - 9.f*vk);
        const float ih10f = exp2f(L2E - 10.f*vk);
        const float ih11f = exp2f(L2E - 11.f*vk);
        const float ih13f = exp2f(L2E - 13.f*vk);
        const float ih16f = exp2f(L2E - 16.f*vk);
        const pf IH7  = PK2(ih7f,ih7f),   IH9  = PK2(ih9f,ih9f);
        const pf IH10 = PK2(ih10f,ih10f), IH11 = PK2(ih11f,ih11f);
        const pf IH13 = PK2(ih13f,ih13f), IH16 = PK2(ih16f,ih16f);

        float* A = (float*)fA; float* B = (float*)fB;
        for (int i = tid; i < 39*39; i += NT){
            int a = i / 39, c = i - a*39;
            float v = src[(oy - 4 + a)*HW + (ox - 4 + c)] * L2E;
            A[(c*PK + (a >> 1))*2 + (a & 1)] = v;
            if (a & 1)       B[(c*PK + (a >> 1))*2]         = v;
            else if (a >= 2) B[(c*PK + (a >> 1) - 1)*2 + 1] = v;
        }
        __syncthreads();

        for (int idx = tid; idx < 34*17; idx += NT){
            int p = idx / 34, x = idx - p*34;
#define RW(r,c) ( ((r) & 1) ? fB[(x+(c))*PK + p + ((r)>>1)] : fA[(x+(c))*PK + p + ((r)>>1)] )
#define TERMP(eA,eB,k) { pf mA,mnA,mB,mnB; mexp((eA),mA,mnA); mexp((eB),mB,mnB); \
                         npair(mnA,mnB,Sn); ipair(mA,mB,IH##k,Si); }
#define TERMS(e,k)     { pf m,mn; mexp((e),m,mn); nsingle(mn,Sn); isingle(m,IH##k,Si); }
            pf Sn = 0ull, Si = 0ull;
            TREE_BODY2
            float S0n,S1n,S0i,S1i; UPK(Sn,S0n,S1n); UPK(Si,S0i,S1i);
            float w0,w1; UPK(RW(3,3), w0, w1);
#undef TERMP
#undef TERMS
#undef RW
            float c00 = w0 * IL2E, c01 = w1 * IL2E;
            int sy = 2*p;
            sS[0][sy*SSP + x]     = sigm10(c00*S0n, 0.5f);
            sS[0][(sy+1)*SSP + x] = sigm10(c01*S1n, 0.5f);
            sS[1][sy*SSP + x]     = sigm10((vmax - c00)*S0i, 0.5f);
            sS[1][(sy+1)*SSP + x] = sigm10((vmax - c01)*S1i, 0.5f);
        }
        __syncthreads();

#pragma unroll
        for (int v = 0; v < 2; ++v)
#pragma unroll
        for (int q = 0; q < 4; ++q){
            int ly = (tid >> 5) + q*8, lx = tid & 31;
            float acc = 0.f;
#pragma unroll
            for (int dy = 0; dy < 3; ++dy)
#pragma unroll
                for (int dx = 0; dx < 3; ++dx)
                    acc += sS[v][(ly+dy)*SSP + lx + dx];
            cp[ts][v][q] = fminf(fmaxf(acc, 0.f), 1.f);
        }
        __syncthreads();
    }

    float local = 0.f;
#pragma unroll
    for (int v = 0; v < 2; ++v)
#pragma unroll
    for (int q = 0; q < 4; ++q){
        float d = cp[0][v][q] - cp[1][v][q];
        local += d*d;
    }
    sR[tid] = local; __syncthreads();
    for (int o = NT/2; o > 0; o >>= 1){
        if (tid < o) sR[tid] += sR[tid+o];
        __syncthreads();
    }
    if (tid == 0)
        g_partial[(blockIdx.z*196) + blockIdx.y*14 + blockIdx.x] = sR[0];
}

// ---------------- boundary: general path ----------------
__global__ __launch_bounds__(NT, 3) void cp_edge_kernel(const float* __restrict__ pred0,
                                                        const float* __restrict__ gt0){
    __shared__ pf    fA[39*PK];
    __shared__ pf    fB[39*PK];
    __shared__ float sS[SSN*SSP];
    __shared__ float sR[NT];
    const int tid = threadIdx.x;
    const int pt  = blockIdx.z >> 3;
    const int b   = blockIdx.z & 7;
    const int level = pt >> 1;
    const int inv   = pt & 1;
    int t = blockIdx.x, bx, by;
    if      (t < 16){ bx = t;      by = 0;      }
    else if (t < 32){ bx = t - 16; by = 15;     }
    else if (t < 46){ bx = 0;      by = t - 31; }
    else            { bx = 15;     by = t - 45; }
    const int oy = by * TS, ox = bx * TS;

    float cp[2][4];
    for (int ts = 0; ts < 2; ++ts){
        const float* base = (ts == 0)
            ? (level == 0 ? pred0 : (level == 1 ? g_pe1 : g_pe2))
            : (level == 0 ? gt0   : (level == 1 ? g_ge1 : g_ge2));
        const float* src = base + b*NPIX;
        float vmax = inv ? __int_as_float(g_vmax[(ts ? 3 : 0) + level]) : 0.f;

        float* A = (float*)fA; float* B = (float*)fB;
        for (int i = tid; i < 39*39; i += NT){
            int a = i / 39, c = i - a*39;
            int qy = oy - 4 + a, qx = ox - 4 + c;
            float v;
            if (qy < -1 || qy > HW || qx < -1 || qx > HW) v = 0.f;
            else if (qy == -1 || qy == HW || qx == -1 || qx == HW) v = L2E;
            else { float u = src[qy*HW + qx]; v = (inv ? vmax - u : u) * L2E; }
            A[(c*PK + (a >> 1))*2 + (a & 1)] = v;
            if (a & 1)       B[(c*PK + (a >> 1))*2]         = v;
            else if (a >= 2) B[(c*PK + (a >> 1) - 1)*2 + 1] = v;
        }
        __syncthreads();

        for (int idx = tid; idx < 34*17; idx += NT){
            int p = idx / 34, x = idx - p*34;
#define RW(r,c) ( ((r) & 1) ? fB[(x+(c))*PK + p + ((r)>>1)] : fA[(x+(c))*PK + p + ((r)>>1)] )
#define TERMP(eA,eB,k) { pf mA,mnA,mB,mnB; mexp((eA),mA,mnA); mexp((eB),mB,mnB); \
                         npair(mnA,mnB,Sn); }
#define TERMS(e,k)     { pf m,mn; mexp((e),m,mn); nsingle(mn,Sn); }
            pf Sn = 0ull;
            TREE_BODY2
            float S0,S1; UPK(Sn,S0,S1);
            float w0,w1; UPK(RW(3,3), w0, w1);
#undef TERMP
#undef TERMS
#undef RW
            float c00 = w0 * IL2E, c01 = w1 * IL2E;
            int sy = 2*p;
            int gy0 = oy + sy - 1, gx = ox + x - 1;
            float s0 = sigm10(c00*S0, 0.5f);
            float s1 = sigm10(c01*S1, 0.5f);
            bool okx = ((unsigned)gx < HW);
            if (!okx || (unsigned)gy0     >= HW) s0 = 0.f;
            if (!okx || (unsigned)(gy0+1) >= HW) s1 = 0.f;
            sS[sy*SSP + x]     = s0;
            sS[(sy+1)*SSP + x] = s1;
        }
        __syncthreads();

#pragma unroll
        for (int q = 0; q < 4; ++q){
            int ly = (tid >> 5) + q*8, lx = tid & 31;
            float acc = 0.f;
#pragma unroll
            for (int dy = 0; dy < 3; ++dy)
#pragma unroll
                for (int dx = 0; dx < 3; ++dx)
                    acc += sS[(ly+dy)*SSP + lx + dx];
            cp[ts][q] = fminf(fmaxf(acc, 0.f), 1.f);
        }
        __syncthreads();
    }

    float local = 0.f;
#pragma unroll
    for (int q = 0; q < 4; ++q){
        float d = cp[0][q] - cp[1][q];
        local += d*d;
    }
    sR[tid] = local; __syncthreads();
    for (int o = NT/2; o > 0; o >>= 1){
        if (tid < o) sR[tid] += sR[tid+o];
        __syncthreads();
    }
    if (tid == 0)
        g_partial[4704 + blockIdx.z*60 + blockIdx.x] = sR[0];
}

// ---------------- deterministic final reduction ----------------
__global__ __launch_bounds__(256) void final_kernel(float* out){
    __shared__ double sh[256];
    double a = 0.0;
    for (int i = threadIdx.x; i < 7584; i += 256) a += (double)g_partial[i];
    sh[threadIdx.x] = a; __syncthreads();
    for (int o = 128; o > 0; o >>= 1){
        if (threadIdx.x < o) sh[threadIdx.x] += sh[threadIdx.x+o];
        __syncthreads();
    }
    if (threadIdx.x == 0) out[0] = (float)(sh[0] * 0.125);
}

// ---------------- launch ----------------
extern "C" void kernel_launch(void* const* d_in, const int* in_sizes, int n_in,
                              void* d_out, int out_size){
    const float* pred = (const float*)d_in[0];
    const float* gt   = (const float*)d_in[1];
    float* out = (float*)d_out;
    (void)in_sizes; (void)n_in; (void)out_size;

    init_kernel<<<1, 32>>>();
    erode_max   <<<dim3(64, 16), 256>>>(pred, gt, 1);
    erode_finish<<<dim3(64, 16), 256>>>(pred, gt, 1);
    erode_max   <<<dim3(64, 16), 256>>>(pred, gt, 2);
    erode_finish<<<dim3(64, 16), 256>>>(pred, gt, 2);
    cp_int_kernel <<<dim3(14, 14, 24), NT>>>(pred, gt);
    cp_edge_kernel<<<dim3(60, 1, 48), NT>>>(pred, gt);
    final_kernel<<<1, 256>>>(out);
}

// round 11
// speedup vs baseline: 1.9719x; 1.0208x over previous
#include <cuda_runtime.h>

#define HW   512
#define NPIX (512*512)

// ---------------- scratch ----------------
__device__ float g_pe1[8*NPIX], g_pe2[8*NPIX];
__device__ float g_ge1[8*NPIX], g_ge2[8*NPIX];
__device__ int   g_tmax[4];
__device__ int   g_vmax[6];
__device__ float g_partial[7680];

#define L2E   14.4269504f
#define HL2E  7.2134752f
#define IL2E  0.069314718f
#define MCL   1048576.f

__device__ __forceinline__ float ex2a(float x){ float r; asm("ex2.approx.ftz.f32 %0, %1;" : "=f"(r) : "f"(x)); return r; }
__device__ __forceinline__ float rcpa(float x){ float r; asm("rcp.approx.ftz.f32 %0, %1;" : "=f"(r) : "f"(x)); return r; }
__device__ __forceinline__ float sigm10(float v, float beta){
    return rcpa(1.f + ex2a((beta - v) * L2E));
}

typedef unsigned long long pf;
__device__ __forceinline__ pf PADD(pf a, pf b){ pf r; asm("add.rn.f32x2 %0, %1, %2;" : "=l"(r) : "l"(a), "l"(b)); return r; }
__device__ __forceinline__ pf PMUL(pf a, pf b){ pf r; asm("mul.rn.f32x2 %0, %1, %2;" : "=l"(r) : "l"(a), "l"(b)); return r; }
__device__ __forceinline__ pf PFMA(pf a, pf b, pf c){ pf r; asm("fma.rn.f32x2 %0, %1, %2, %3;" : "=l"(r) : "l"(a), "l"(b), "l"(c)); return r; }
__device__ __forceinline__ pf PK2(float lo, float hi){ pf r; asm("mov.b64 %0, {%1, %2};" : "=l"(r) : "f"(lo), "f"(hi)); return r; }
__device__ __forceinline__ void UPK(pf a, float& lo, float& hi){ asm("mov.b64 {%0, %1}, %2;" : "=f"(lo), "=f"(hi) : "l"(a)); }

#define C_ONE2  PK2(1.f,1.f)
#define C_TWO2  PK2(2.f,2.f)
#define C_HALF2 PK2(0.5f,0.5f)
#define C_NH2   PK2(-HL2E,-HL2E)

__device__ __forceinline__ void mexp(pf w2, pf& m2, pf& mn2){
    pf u2 = PFMA(w2, C_HALF2, C_NH2);
    float u0,u1; UPK(u2,u0,u1);
    float m0 = ex2a(u0), m1 = ex2a(u1);
    m2  = PK2(m0, m1);
    mn2 = PK2(fminf(m0,MCL), fminf(m1,MCL));
}
__device__ __forceinline__ void npair(pf mnA, pf mnB, pf& Sn){
    pf eA = PMUL(mnA,mnA), eB = PMUL(mnB,mnB);
    pf s  = PADD(eA,eB);
    pf d  = PFMA(eA, eB, PADD(C_ONE2, s));
    pf n  = PADD(C_TWO2, s);
    float d0,d1; UPK(d,d0,d1);
    Sn = PFMA(n, PK2(rcpa(d0),rcpa(d1)), Sn);
}
__device__ __forceinline__ void ipair(pf mA, pf mB, pf ih, pf& Si){
    pf qA = PMUL(mA, ih), qB = PMUL(mB, ih);
    pf a  = PMUL(qA,qA),  b  = PMUL(qB,qB);
    pf s  = PADD(a,b);
    pf p  = PMUL(a,b);
    pf d  = PADD(PADD(C_ONE2,s), p);
    pf n  = PFMA(p, C_TWO2, s);
    float d0,d1; UPK(d,d0,d1);
    Si = PFMA(n, PK2(rcpa(d0),rcpa(d1)), Si);
}
__device__ __forceinline__ void nsingle(pf mn, pf& Sn){
    pf e = PMUL(mn,mn);
    pf d = PADD(C_ONE2, e);
    float d0,d1; UPK(d,d0,d1);
    Sn = PADD(Sn, PK2(rcpa(d0),rcpa(d1)));
}
__device__ __forceinline__ void isingle(pf m, pf ih, pf& Si){
    pf q = PMUL(m, ih);
    pf a = PMUL(q,q);
    pf d = PADD(C_ONE2, a);
    float d0,d1; UPK(d,d0,d1);
    Si = PFMA(a, PK2(rcpa(d0),rcpa(d1)), Si);
}

// ---------------- geometry ----------------
#define SSN 34
#define SSP 35
#define NT  256
#define TS  32
#define PK  21

#define TREE_BODY2                                                                 \
    {   /* K6 */                                                                   \
        pf a0=RW(0,0),b0=RW(0,1),c0_=RW(0,2),d0=RW(0,3),e0=RW(0,4),f0=RW(0,5);     \
        pf a1=RW(1,0),f1=RW(1,5);                                                  \
        pf a2=RW(2,0),f2=RW(2,5);                                                  \
        pf a3=RW(3,0),f3=RW(3,5);                                                  \
        pf a4=RW(4,0),f4=RW(4,5);                                                  \
        pf a5=RW(5,0),b5=RW(5,1),c5=RW(5,2),d5=RW(5,3),e5=RW(5,4),f5=RW(5,5);      \
        pf r0_03=PADD(e0,f0), r0_30=PADD(a0,b0);                                   \
        pf r0_66=PADD(PADD(r0_30,PADD(c0_,d0)),r0_03);                             \
        pf r5_03=PADD(e5,f5), r5_30=PADD(a5,b5);                                   \
        pf r5_66=PADD(PADD(r5_30,PADD(c5,d5)),r5_03), r5_s=PADD(a5,f5);            \
        pf r1_s=PADD(a1,f1), r2_s=PADD(a2,f2), r3_s=PADD(a3,f3), r4_s=PADD(a4,f4); \
        pf t23a=PADD(a2,a3), t123a=PADD(a1,t23a), t234a=PADD(t23a,a4);             \
        pf t23f=PADD(f2,f3), t123f=PADD(f1,t23f), t234f=PADD(t23f,f4);             \
        TERMP(PADD(PADD(r0_03,t123f),PADD(r4_s,r5_66)),                            \
              PADD(PADD(r0_30,t123a),PADD(r4_s,r5_66)), 13)                        \
        TERMP(PADD(PADD(r0_66,r1_s),PADD(t234a,r5_30)),                            \
              PADD(PADD(r0_66,r1_s),PADD(t234f,r5_03)), 13)                        \
        TERMP(PADD(PADD(r0_66,t123a),PADD(a4,r5_66)),                              \
              PADD(PADD(r0_66,t123f),PADD(f4,r5_66)), 16)                          \
        TERMS(PADD(PADD(r0_66,PADD(r1_s,r2_s)),PADD(PADD(r3_s,r4_s),r5_s)), 16)    \
    }                                                                              \
    {   /* K5 */                                                                   \
        pf a1=RW(1,1),b1=RW(1,2),c1=RW(1,3),d1=RW(1,4),e1=RW(1,5);                 \
        pf a2=RW(2,1),e2=RW(2,5);                                                  \
        pf a3=RW(3,1),e3=RW(3,5);                                                  \
        pf a4=RW(4,1),e4=RW(4,5);                                                  \
        pf a5=RW(5,1),b5=RW(5,2),c5=RW(5,3),d5=RW(5,4),e5=RW(5,5);                 \
        pf r1_02=PADD(d1,e1), r1_20=PADD(a1,b1);                                   \
        pf r1_55=PADD(PADD(r1_20,c1),r1_02), r1_s=PADD(a1,e1);                     \
        pf q2=PADD(a2,e2), q3=PADD(a3,e3), q4=PADD(a4,e4);                         \
        pf r5_02=PADD(d5,e5), r5_20=PADD(a5,b5);                                   \
        pf r5_55=PADD(PADD(r5_20,c5),r5_02), r5_s=PADD(a5,e5);                     \
        pf t23a=PADD(a2,a3), t23e=PADD(e2,e3), t234=PADD(PADD(q2,q3),q4);          \
        TERMP(PADD(PADD(r1_02,t23e),PADD(q4,r5_55)),                               \
              PADD(PADD(r1_20,t23a),PADD(q4,r5_55)), 11)                           \
        TERMP(PADD(PADD(r1_55,q2),PADD(PADD(a3,a4),r5_20)),                        \
              PADD(PADD(r1_55,q2),PADD(PADD(e3,e4),r5_02)), 11)                    \
        TERMP(PADD(PADD(r1_55,t23a),PADD(a4,r5_55)),                               \
              PADD(PADD(r1_55,t23e),PADD(e4,r5_55)), 13)                           \
        TERMP(PADD(PADD(r1_55,t234),r5_s),                                         \
              PADD(PADD(r1_s,t234),r5_55), 13)                                     \
    }                                                                              \
    {   /* K4 */                                                                   \
        pf a1=RW(1,1),b1=RW(1,2),c1=RW(1,3),d1=RW(1,4);                            \
        pf a2=RW(2,1),d2=RW(2,4);                                                  \
        pf a3=RW(3,1),d3=RW(3,4);                                                  \
        pf a4=RW(4,1),b4=RW(4,2),c4=RW(4,3),d4=RW(4,4);                            \
        pf r1_01=PADD(c1,d1), r1_10=PADD(a1,b1), r1_44=PADD(r1_01,r1_10), r1_s=PADD(a1,d1); \
        pf q2=PADD(a2,d2), q3=PADD(a3,d3);                                         \
        pf r4_01=PADD(c4,d4), r4_10=PADD(a4,b4), r4_44=PADD(r4_01,r4_10), r4_s=PADD(a4,d4); \
        pf t23=PADD(q2,q3);                                                        \
        TERMP(PADD(PADD(r1_01,d2),PADD(q3,r4_44)),                                 \
              PADD(PADD(r1_10,a2),PADD(q3,r4_44)), 9)                              \
        TERMP(PADD(PADD(r1_44,q2),PADD(d3,r4_01)),                                 \
              PADD(PADD(r1_44,q2),PADD(a3,r4_10)), 9)                              \
        TERMP(PADD(PADD(r1_s,t23),r4_44),                                          \
              PADD(PADD(r1_44,PADD(d2,d3)),r4_44), 10)                             \
        TERMP(PADD(PADD(r1_44,t23),r4_s),                                          \
              PADD(PADD(r1_44,PADD(a2,a3)),r4_44), 10)                             \
    }                                                                              \
    {   /* K3 */                                                                   \
        pf a2=RW(2,2),b2=RW(2,3),c2=RW(2,4);                                       \
        pf a3=RW(3,2),c3=RW(3,4);                                                  \
        pf a4=RW(4,2),b4=RW(4,3),c4=RW(4,4);                                       \
        pf r2_10=PADD(a2,b2), r2_33=PADD(r2_10,c2), r2_s=PADD(a2,c2), r2_01=PADD(b2,c2); \
        pf q3=PADD(a3,c3);                                                         \
        pf r4_10=PADD(a4,b4), r4_33=PADD(r4_10,c4), r4_s=PADD(a4,c4), r4_01=PADD(b4,c4); \
        TERMP(PADD(PADD(r2_33,c3),r4_33), PADD(PADD(r2_33,q3),r4_s), 7)            \
        TERMP(PADD(PADD(r2_33,a3),r4_33), PADD(PADD(r2_s,q3),r4_33), 7)            \
        TERMP(PADD(PADD(r2_01,q3),r4_33), PADD(PADD(r2_33,q3),r4_01), 7)           \
        TERMP(PADD(PADD(r2_33,q3),r4_10), PADD(PADD(r2_10,q3),r4_33), 7)           \
    }

// ---------------- init ----------------
__global__ void init_kernel(){
    int t = threadIdx.x;
    if (t < 4) g_tmax[t] = 0;
    if (t < 6) g_vmax[t] = 0;
}

// ---------------- erosion pass A ----------------
__global__ __launch_bounds__(256) void erode_max(const float* __restrict__ psrc,
                                                 const float* __restrict__ gsrc,
                                                 int lvl){
    __shared__ float sW[8], sW2[8];
    const int img = blockIdx.y;
    const float* src;
    if (lvl == 1) src = (img < 8) ? psrc + img*NPIX : gsrc + (img-8)*NPIX;
    else          src = (img < 8) ? g_pe1 + img*NPIX : g_ge1 + (img-8)*NPIX;
    const int tid = threadIdx.x;
    float mt = 0.f, mr = 0.f;
#pragma unroll
    for (int k = 0; k < 4; ++k){
        int base = blockIdx.x*4096 + k*1024 + tid*4;
        int y = base >> 9, x = base & 511;
        float4 mid = *(const float4*)(src + base);
        float4 up  = (y > 0)    ? *(const float4*)(src + base - HW) : make_float4(0,0,0,0);
        float4 dn  = (y < HW-1) ? *(const float4*)(src + base + HW) : make_float4(0,0,0,0);
        float  lf  = (x > 0)    ? src[base - 1] : 0.f;
        float  rt  = (x < 508)  ? src[base + 4] : 0.f;
        float t0 = up.x + dn.x + lf    + mid.y;
        float t1 = up.y + dn.y + mid.x + mid.z;
        float t2 = up.z + dn.z + mid.y + mid.w;
        float t3 = up.w + dn.w + mid.z + rt;
        mt = fmaxf(mt, fmaxf(fmaxf(t0,t1), fmaxf(t2,t3)));
        if (lvl == 1) mr = fmaxf(mr, fmaxf(fmaxf(mid.x,mid.y), fmaxf(mid.z,mid.w)));
    }
#pragma unroll
    for (int o = 16; o > 0; o >>= 1){
        mt = fmaxf(mt, __shfl_xor_sync(0xffffffffu, mt, o));
        mr = fmaxf(mr, __shfl_xor_sync(0xffffffffu, mr, o));
    }
    if ((tid & 31) == 0){ sW[tid>>5] = mt; sW2[tid>>5] = mr; }
    __syncthreads();
    if (tid == 0){
#pragma unroll
        for (int i = 1; i < 8; ++i){ mt = fmaxf(mt, sW[i]); mr = fmaxf(mr, sW2[i]); }
        atomicMax(&g_tmax[2*(lvl-1) + (img < 8 ? 0 : 1)], __float_as_int(mt));
        if (lvl == 1) atomicMax(&g_vmax[img < 8 ? 0 : 3], __float_as_int(mr));
    }
}

// ---------------- erosion pass B ----------------
__global__ __launch_bounds__(256) void erode_finish(const float* __restrict__ psrc,
                                                    const float* __restrict__ gsrc,
                                                    int lvl){
    __shared__ float sW[8];
    const int img = blockIdx.y;
    const float* src;
    float* dst;
    if (lvl == 1){ src = (img < 8) ? psrc + img*NPIX : gsrc + (img-8)*NPIX;
                   dst = (img < 8) ? g_pe1 + img*NPIX : g_ge1 + (img-8)*NPIX; }
    else         { src = (img < 8) ? g_pe1 + img*NPIX : g_ge1 + (img-8)*NPIX;
                   dst = (img < 8) ? g_pe2 + img*NPIX : g_ge2 + (img-8)*NPIX; }
    const int tid = threadIdx.x;
    const float tmax = __int_as_float(g_tmax[2*(lvl-1) + (img < 8 ? 0 : 1)]);
    const float inv = __frcp_rn(tmax + 1e-8f);
    float mv = 0.f;
#pragma unroll
    for (int k = 0; k < 4; ++k){
        int base = blockIdx.x*4096 + k*1024 + tid*4;
        int y = base >> 9, x = base & 511;
        float4 mid = *(const float4*)(src + base);
        float4 up  = (y > 0)    ? *(const float4*)(src + base - HW) : make_float4(0,0,0,0);
        float4 dn  = (y < HW-1) ? *(const float4*)(src + base + HW) : make_float4(0,0,0,0);
        float  lf  = (x > 0)    ? src[base - 1] : 0.f;
        float  rt  = (x < 508)  ? src[base + 4] : 0.f;
        float4 v;
        v.x = sigm10((up.x + dn.x + lf    + mid.y) * inv, 0.7f);
        v.y = sigm10((up.y + dn.y + mid.x + mid.z) * inv, 0.7f);
        v.z = sigm10((up.z + dn.z + mid.y + mid.w) * inv, 0.7f);
        v.w = sigm10((up.w + dn.w + mid.z + rt   ) * inv, 0.7f);
        *(float4*)(dst + base) = v;
        mv = fmaxf(mv, fmaxf(fmaxf(v.x,v.y), fmaxf(v.z,v.w)));
    }
#pragma unroll
    for (int o = 16; o > 0; o >>= 1) mv = fmaxf(mv, __shfl_xor_sync(0xffffffffu, mv, o));
    if ((tid & 31) == 0) sW[tid >> 5] = mv;
    __syncthreads();
    if (tid == 0){
#pragma unroll
        for (int i = 1; i < 8; ++i) mv = fmaxf(mv, sW[i]);
        atomicMax(&g_vmax[(img < 8 ? 0 : 3) + lvl], __float_as_int(mv));
    }
}

// ---------------- interior: merged inv0+inv1, shared exponentials ----------------
__global__ __launch_bounds__(NT, 3) void cp_int_kernel(const float* __restrict__ pred0,
                                                       const float* __restrict__ gt0){
    __shared__ pf    fA[39*PK];
    __shared__ pf    fB[39*PK];
    __shared__ float sS[2][SSN*SSP];
    __shared__ float sW[8];
    const int tid = threadIdx.x;
    const int level = blockIdx.z >> 3;
    const int b     = blockIdx.z & 7;
    const int oy = (blockIdx.y + 1) * TS, ox = (blockIdx.x + 1) * TS;

    float cp[2][2][4];
    for (int ts = 0; ts < 2; ++ts){
        const float* base = (ts == 0)
            ? (level == 0 ? pred0 : (level == 1 ? g_pe1 : g_pe2))
            : (level == 0 ? gt0   : (level == 1 ? g_ge1 : g_ge2));
        const float* src = base + b*NPIX;
        const float vmax = __int_as_float(g_vmax[(ts ? 3 : 0) + level]);
        const float vk = HL2E * vmax;
        const float ih7f  = exp2f(L2E - 7.f*vk);
        const float ih9f  = exp2f(L2E - 9.f*vk);
        const float ih10f = exp2f(L2E - 10.f*vk);
        const float ih11f = exp2f(L2E - 11.f*vk);
        const float ih13f = exp2f(L2E - 13.f*vk);
        const float ih16f = exp2f(L2E - 16.f*vk);
        const pf IH7  = PK2(ih7f,ih7f),   IH9  = PK2(ih9f,ih9f);
        const pf IH10 = PK2(ih10f,ih10f), IH11 = PK2(ih11f,ih11f);
        const pf IH13 = PK2(ih13f,ih13f), IH16 = PK2(ih16f,ih16f);

        float* A = (float*)fA; float* B = (float*)fB;
        for (int i = tid; i < 39*39; i += NT){
            int a = i / 39, c = i - a*39;
            float v = src[(oy - 4 + a)*HW + (ox - 4 + c)] * L2E;
            A[(c*PK + (a >> 1))*2 + (a & 1)] = v;
            if (a & 1)       B[(c*PK + (a >> 1))*2]         = v;
            else if (a >= 2) B[(c*PK + (a >> 1) - 1)*2 + 1] = v;
        }
        __syncthreads();

        for (int idx = tid; idx < 34*17; idx += NT){
            int p = idx / 34, x = idx - p*34;
#define RW(r,c) ( ((r) & 1) ? fB[(x+(c))*PK + p + ((r)>>1)] : fA[(x+(c))*PK + p + ((r)>>1)] )
#define TERMP(eA,eB,k) { pf mA,mnA,mB,mnB; mexp((eA),mA,mnA); mexp((eB),mB,mnB); \
                         npair(mnA,mnB,Sn); ipair(mA,mB,IH##k,Si); }
#define TERMS(e,k)     { pf m,mn; mexp((e),m,mn); nsingle(mn,Sn); isingle(m,IH##k,Si); }
            pf Sn = 0ull, Si = 0ull;
            TREE_BODY2
            float S0n,S1n,S0i,S1i; UPK(Sn,S0n,S1n); UPK(Si,S0i,S1i);
            float w0,w1; UPK(RW(3,3), w0, w1);
#undef TERMP
#undef TERMS
#undef RW
            float c00 = w0 * IL2E, c01 = w1 * IL2E;
            int sy = 2*p;
            sS[0][sy*SSP + x]     = sigm10(c00*S0n, 0.5f);
            sS[0][(sy+1)*SSP + x] = sigm10(c01*S1n, 0.5f);
            sS[1][sy*SSP + x]     = sigm10((vmax - c00)*S0i, 0.5f);
            sS[1][(sy+1)*SSP + x] = sigm10((vmax - c01)*S1i, 0.5f);
        }
        __syncthreads();

        // dilate both variants: 2048 outputs
        for (int idx = tid, j = 0; idx < 2048; idx += NT, ++j){
            int v = idx >> 10, r = idx & 1023;
            int ly = r >> 5, lx = r & 31;
            float acc = 0.f;
#pragma unroll
            for (int dy = 0; dy < 3; ++dy)
#pragma unroll
                for (int dx = 0; dx < 3; ++dx)
                    acc += sS[v][(ly+dy)*SSP + lx + dx];
            acc = fminf(fmaxf(acc, 0.f), 1.f);
            cp[ts][j >> 2][j & 3] = acc;
        }
        __syncthreads();
    }

    float local = 0.f;
#pragma unroll
    for (int v = 0; v < 2; ++v)
#pragma unroll
    for (int q = 0; q < 4; ++q){
        float d = cp[0][v][q] - cp[1][v][q];
        local += d*d;
    }
#pragma unroll
    for (int o = 16; o > 0; o >>= 1) local += __shfl_xor_sync(0xffffffffu, local, o);
    if ((tid & 31) == 0) sW[tid >> 5] = local;
    __syncthreads();
    if (tid == 0){
        float s = sW[0];
#pragma unroll
        for (int i = 1; i < 8; ++i) s += sW[i];
        g_partial[(blockIdx.z*196) + blockIdx.y*14 + blockIdx.x] = s;
    }
}

// ---------------- boundary: general path ----------------
__global__ __launch_bounds__(NT, 3) void cp_edge_kernel(const float* __restrict__ pred0,
                                                        const float* __restrict__ gt0){
    __shared__ pf    fA[39*PK];
    __shared__ pf    fB[39*PK];
    __shared__ float sS[SSN*SSP];
    __shared__ float sW[8];
    const int tid = threadIdx.x;
    const int pt  = blockIdx.z >> 3;
    const int b   = blockIdx.z & 7;
    const int level = pt >> 1;
    const int inv   = pt & 1;
    int t = blockIdx.x, bx, by;
    if      (t < 16){ bx = t;      by = 0;      }
    else if (t < 32){ bx = t - 16; by = 15;     }
    else if (t < 46){ bx = 0;      by = t - 31; }
    else            { bx = 15;     by = t - 45; }
    const int oy = by * TS, ox = bx * TS;

    float cp[2][4];
    for (int ts = 0; ts < 2; ++ts){
        const float* base = (ts == 0)
            ? (level == 0 ? pred0 : (level == 1 ? g_pe1 : g_pe2))
            : (level == 0 ? gt0   : (level == 1 ? g_ge1 : g_ge2));
        const float* src = base + b*NPIX;
        float vmax = inv ? __int_as_float(g_vmax[(ts ? 3 : 0) + level]) : 0.f;

        float* A = (float*)fA; float* B = (float*)fB;
        for (int i = tid; i < 39*39; i += NT){
            int a = i / 39, c = i - a*39;
            int qy = oy - 4 + a, qx = ox - 4 + c;
            float v;
            if (qy < -1 || qy > HW || qx < -1 || qx > HW) v = 0.f;
            else if (qy == -1 || qy == HW || qx == -1 || qx == HW) v = L2E;
            else { float u = src[qy*HW + qx]; v = (inv ? vmax - u : u) * L2E; }
            A[(c*PK + (a >> 1))*2 + (a & 1)] = v;
            if (a & 1)       B[(c*PK + (a >> 1))*2]         = v;
            else if (a >= 2) B[(c*PK + (a >> 1) - 1)*2 + 1] = v;
        }
        __syncthreads();

        for (int idx = tid; idx < 34*17; idx += NT){
            int p = idx / 34, x = idx - p*34;
#define RW(r,c) ( ((r) & 1) ? fB[(x+(c))*PK + p + ((r)>>1)] : fA[(x+(c))*PK + p + ((r)>>1)] )
#define TERMP(eA,eB,k) { pf mA,mnA,mB,mnB; mexp((eA),mA,mnA); mexp((eB),mB,mnB); \
                         npair(mnA,mnB,Sn); }
#define TERMS(e,k)     { pf m,mn; mexp((e),m,mn); nsingle(mn,Sn); }
            pf Sn = 0ull;
            TREE_BODY2
            float S0,S1; UPK(Sn,S0,S1);
            float w0,w1; UPK(RW(3,3), w0, w1);
#undef TERMP
#undef TERMS
#undef RW
            float c00 = w0 * IL2E, c01 = w1 * IL2E;
            int sy = 2*p;
            int gy0 = oy + sy - 1, gx = ox + x - 1;
            float s0 = sigm10(c00*S0, 0.5f);
            float s1 = sigm10(c01*S1, 0.5f);
            bool okx = ((unsigned)gx < HW);
            if (!okx || (unsigned)gy0     >= HW) s0 = 0.f;
            if (!okx || (unsigned)(gy0+1) >= HW) s1 = 0.f;
            sS[sy*SSP + x]     = s0;
            sS[(sy+1)*SSP + x] = s1;
        }
        __syncthreads();

#pragma unroll
        for (int q = 0; q < 4; ++q){
            int ly = (tid >> 5) + q*8, lx = tid & 31;
            float acc = 0.f;
#pragma unroll
            for (int dy = 0; dy < 3; ++dy)
#pragma unroll
                for (int dx = 0; dx < 3; ++dx)
                    acc += sS[(ly+dy)*SSP + lx + dx];
            cp[ts][q] = fminf(fmaxf(acc, 0.f), 1.f);
        }
        __syncthreads();
    }

    float local = 0.f;
#pragma unroll
    for (int q = 0; q < 4; ++q){
        float d = cp[0][q] - cp[1][q];
        local += d*d;
    }
#pragma unroll
    for (int o = 16; o > 0; o >>= 1) local += __shfl_xor_sync(0xffffffffu, local, o);
    if ((tid & 31) == 0) sW[tid >> 5] = local;
    __syncthreads();
    if (tid == 0){
        float s = sW[0];
#pragma unroll
        for (int i = 1; i < 8; ++i) s += sW[i];
        g_partial[4704 + blockIdx.z*60 + blockIdx.x] = s;
    }
}

// ---------------- deterministic final reduction ----------------
__global__ __launch_bounds__(256) void final_kernel(float* out){
    __shared__ double sh[256];
    double a = 0.0;
    for (int i = threadIdx.x; i < 7584; i += 256) a += (double)g_partial[i];
    sh[threadIdx.x] = a; __syncthreads();
    for (int o = 128; o > 0; o >>= 1){
        if (threadIdx.x < o) sh[threadIdx.x] += sh[threadIdx.x+o];
        __syncthreads();
    }
    if (threadIdx.x == 0) out[0] = (float)(sh[0] * 0.125);
}

// ---------------- launch ----------------
extern "C" void kernel_launch(void* const* d_in, const int* in_sizes, int n_in,
                              void* d_out, int out_size){
    const float* pred = (const float*)d_in[0];
    const float* gt   = (const float*)d_in[1];
    float* out = (float*)d_out;
    (void)in_sizes; (void)n_in; (void)out_size;

    init_kernel<<<1, 32>>>();
    erode_max   <<<dim3(64, 16), 256>>>(pred, gt, 1);
    erode_finish<<<dim3(64, 16), 256>>>(pred, gt, 1);
    erode_max   <<<dim3(64, 16), 256>>>(pred, gt, 2);
    erode_finish<<<dim3(64, 16), 256>>>(pred, gt, 2);
    cp_int_kernel <<<dim3(14, 14, 24), NT>>>(pred, gt);
    cp_edge_kernel<<<dim3(60, 1, 48), NT>>>(pred, gt);
    final_kernel<<<1, 256>>>(out);
}

// round 13
// speedup vs baseline: 2.0899x; 1.0598x over previous
#include <cuda_runtime.h>

#define HW   512
#define NPIX (512*512)

// ---------------- scratch ----------------
__device__ float g_pe1[8*NPIX], g_pe2[8*NPIX];
__device__ float g_ge1[8*NPIX], g_ge2[8*NPIX];
__device__ int   g_tmax[4];
__device__ int   g_vmax[6];
__device__ float g_partial[7680];

#define L2E   14.4269504f
#define HL2E  7.2134752f
#define IL2E  0.069314718f
#define MCL   1048576.f

__device__ __forceinline__ float ex2a(float x){ float r; asm("ex2.approx.ftz.f32 %0, %1;" : "=f"(r) : "f"(x)); return r; }
__device__ __forceinline__ float rcpa(float x){ float r; asm("rcp.approx.ftz.f32 %0, %1;" : "=f"(r) : "f"(x)); return r; }
__device__ __forceinline__ float sigm10(float v, float beta){
    return rcpa(1.f + ex2a((beta - v) * L2E));
}

typedef unsigned long long pf;
__device__ __forceinline__ pf PADD(pf a, pf b){ pf r; asm("add.rn.f32x2 %0, %1, %2;" : "=l"(r) : "l"(a), "l"(b)); return r; }
__device__ __forceinline__ pf PMUL(pf a, pf b){ pf r; asm("mul.rn.f32x2 %0, %1, %2;" : "=l"(r) : "l"(a), "l"(b)); return r; }
__device__ __forceinline__ pf PFMA(pf a, pf b, pf c){ pf r; asm("fma.rn.f32x2 %0, %1, %2, %3;" : "=l"(r) : "l"(a), "l"(b), "l"(c)); return r; }
__device__ __forceinline__ pf PK2(float lo, float hi){ pf r; asm("mov.b64 %0, {%1, %2};" : "=l"(r) : "f"(lo), "f"(hi)); return r; }
__device__ __forceinline__ void UPK(pf a, float& lo, float& hi){ asm("mov.b64 {%0, %1}, %2;" : "=f"(lo), "=f"(hi) : "l"(a)); }

#define C_ONE2  PK2(1.f,1.f)
#define C_TWO2  PK2(2.f,2.f)
#define C_HALF2 PK2(0.5f,0.5f)
#define C_NH2   PK2(-HL2E,-HL2E)

__device__ __forceinline__ void mexp(pf w2, pf& m2, pf& mn2){
    pf u2 = PFMA(w2, C_HALF2, C_NH2);
    float u0,u1; UPK(u2,u0,u1);
    float m0 = ex2a(u0), m1 = ex2a(u1);
    m2  = PK2(m0, m1);
    mn2 = PK2(fminf(m0,MCL), fminf(m1,MCL));
}
__device__ __forceinline__ void npair(pf mnA, pf mnB, pf& Sn){
    pf eA = PMUL(mnA,mnA), eB = PMUL(mnB,mnB);
    pf s  = PADD(eA,eB);
    pf d  = PFMA(eA, eB, PADD(C_ONE2, s));
    pf n  = PADD(C_TWO2, s);
    float d0,d1; UPK(d,d0,d1);
    Sn = PFMA(n, PK2(rcpa(d0),rcpa(d1)), Sn);
}
__device__ __forceinline__ void ipair(pf mA, pf mB, pf ih, pf& Si){
    pf qA = PMUL(mA, ih), qB = PMUL(mB, ih);
    pf a  = PMUL(qA,qA),  b  = PMUL(qB,qB);
    pf s  = PADD(a,b);
    pf p  = PMUL(a,b);
    pf d  = PADD(PADD(C_ONE2,s), p);
    pf n  = PFMA(p, C_TWO2, s);
    float d0,d1; UPK(d,d0,d1);
    Si = PFMA(n, PK2(rcpa(d0),rcpa(d1)), Si);
}
__device__ __forceinline__ void nsingle(pf mn, pf& Sn){
    pf e = PMUL(mn,mn);
    pf d = PADD(C_ONE2, e);
    float d0,d1; UPK(d,d0,d1);
    Sn = PADD(Sn, PK2(rcpa(d0),rcpa(d1)));
}
__device__ __forceinline__ void isingle(pf m, pf ih, pf& Si){
    pf q = PMUL(m, ih);
    pf a = PMUL(q,q);
    pf d = PADD(C_ONE2, a);
    float d0,d1; UPK(d,d0,d1);
    Si = PFMA(a, PK2(rcpa(d0),rcpa(d1)), Si);
}

// ---------------- geometry ----------------
#define SSN 34
#define SSP 35
#define NT  256
#define TS  32
#define PK  21

#define TREE_BODY2                                                                 \
    {   /* K6 */                                                                   \
        pf a0=RW(0,0),b0=RW(0,1),c0_=RW(0,2),d0=RW(0,3),e0=RW(0,4),f0=RW(0,5);     \
        pf a1=RW(1,0),f1=RW(1,5);                                                  \
        pf a2=RW(2,0),f2=RW(2,5);                                                  \
        pf a3=RW(3,0),f3=RW(3,5);                                                  \
        pf a4=RW(4,0),f4=RW(4,5);                                                  \
        pf a5=RW(5,0),b5=RW(5,1),c5=RW(5,2),d5=RW(5,3),e5=RW(5,4),f5=RW(5,5);      \
        pf r0_03=PADD(e0,f0), r0_30=PADD(a0,b0);                                   \
        pf r0_66=PADD(PADD(r0_30,PADD(c0_,d0)),r0_03);                             \
        pf r5_03=PADD(e5,f5), r5_30=PADD(a5,b5);                                   \
        pf r5_66=PADD(PADD(r5_30,PADD(c5,d5)),r5_03), r5_s=PADD(a5,f5);            \
        pf r1_s=PADD(a1,f1), r2_s=PADD(a2,f2), r3_s=PADD(a3,f3), r4_s=PADD(a4,f4); \
        pf t23a=PADD(a2,a3), t123a=PADD(a1,t23a), t234a=PADD(t23a,a4);             \
        pf t23f=PADD(f2,f3), t123f=PADD(f1,t23f), t234f=PADD(t23f,f4);             \
        TERMP(PADD(PADD(r0_03,t123f),PADD(r4_s,r5_66)),                            \
              PADD(PADD(r0_30,t123a),PADD(r4_s,r5_66)), 13)                        \
        TERMP(PADD(PADD(r0_66,r1_s),PADD(t234a,r5_30)),                            \
              PADD(PADD(r0_66,r1_s),PADD(t234f,r5_03)), 13)                        \
        TERMP(PADD(PADD(r0_66,t123a),PADD(a4,r5_66)),                              \
              PADD(PADD(r0_66,t123f),PADD(f4,r5_66)), 16)                          \
        TERMS(PADD(PADD(r0_66,PADD(r1_s,r2_s)),PADD(PADD(r3_s,r4_s),r5_s)), 16)    \
    }                                                                              \
    {   /* K5 */                                                                   \
        pf a1=RW(1,1),b1=RW(1,2),c1=RW(1,3),d1=RW(1,4),e1=RW(1,5);                 \
        pf a2=RW(2,1),e2=RW(2,5);                                                  \
        pf a3=RW(3,1),e3=RW(3,5);                                                  \
        pf a4=RW(4,1),e4=RW(4,5);                                                  \
        pf a5=RW(5,1),b5=RW(5,2),c5=RW(5,3),d5=RW(5,4),e5=RW(5,5);                 \
        pf r1_02=PADD(d1,e1), r1_20=PADD(a1,b1);                                   \
        pf r1_55=PADD(PADD(r1_20,c1),r1_02), r1_s=PADD(a1,e1);                     \
        pf q2=PADD(a2,e2), q3=PADD(a3,e3), q4=PADD(a4,e4);                         \
        pf r5_02=PADD(d5,e5), r5_20=PADD(a5,b5);                                   \
        pf r5_55=PADD(PADD(r5_20,c5),r5_02), r5_s=PADD(a5,e5);                     \
        pf t23a=PADD(a2,a3), t23e=PADD(e2,e3), t234=PADD(PADD(q2,q3),q4);          \
        TERMP(PADD(PADD(r1_02,t23e),PADD(q4,r5_55)),                               \
              PADD(PADD(r1_20,t23a),PADD(q4,r5_55)), 11)                           \
        TERMP(PADD(PADD(r1_55,q2),PADD(PADD(a3,a4),r5_20)),                        \
              PADD(PADD(r1_55,q2),PADD(PADD(e3,e4),r5_02)), 11)                    \
        TERMP(PADD(PADD(r1_55,t23a),PADD(a4,r5_55)),                               \
              PADD(PADD(r1_55,t23e),PADD(e4,r5_55)), 13)                           \
        TERMP(PADD(PADD(r1_55,t234),r5_s),                                         \
              PADD(PADD(r1_s,t234),r5_55), 13)                                     \
    }                                                                              \
    {   /* K4 */                                                                   \
        pf a1=RW(1,1),b1=RW(1,2),c1=RW(1,3),d1=RW(1,4);                            \
        pf a2=RW(2,1),d2=RW(2,4);                                                  \
        pf a3=RW(3,1),d3=RW(3,4);                                                  \
        pf a4=RW(4,1),b4=RW(4,2),c4=RW(4,3),d4=RW(4,4);                            \
        pf r1_01=PADD(c1,d1), r1_10=PADD(a1,b1), r1_44=PADD(r1_01,r1_10), r1_s=PADD(a1,d1); \
        pf q2=PADD(a2,d2), q3=PADD(a3,d3);                                         \
        pf r4_01=PADD(c4,d4), r4_10=PADD(a4,b4), r4_44=PADD(r4_01,r4_10), r4_s=PADD(a4,d4); \
        pf t23=PADD(q2,q3);                                                        \
        TERMP(PADD(PADD(r1_01,d2),PADD(q3,r4_44)),                                 \
              PADD(PADD(r1_10,a2),PADD(q3,r4_44)), 9)                              \
        TERMP(PADD(PADD(r1_44,q2),PADD(d3,r4_01)),                                 \
              PADD(PADD(r1_44,q2),PADD(a3,r4_10)), 9)                              \
        TERMP(PADD(PADD(r1_s,t23),r4_44),                                          \
              PADD(PADD(r1_44,PADD(d2,d3)),r4_44), 10)                             \
        TERMP(PADD(PADD(r1_44,t23),r4_s),                                          \
              PADD(PADD(r1_44,PADD(a2,a3)),r4_44), 10)                             \
    }                                                                              \
    {   /* K3 */                                                                   \
        pf a2=RW(2,2),b2=RW(2,3),c2=RW(2,4);                                       \
        pf a3=RW(3,2),c3=RW(3,4);                                                  \
        pf a4=RW(4,2),b4=RW(4,3),c4=RW(4,4);                                       \
        pf r2_10=PADD(a2,b2), r2_33=PADD(r2_10,c2), r2_s=PADD(a2,c2), r2_01=PADD(b2,c2); \
        pf q3=PADD(a3,c3);                                                         \
        pf r4_10=PADD(a4,b4), r4_33=PADD(r4_10,c4), r4_s=PADD(a4,c4), r4_01=PADD(b4,c4); \
        TERMP(PADD(PADD(r2_33,c3),r4_33), PADD(PADD(r2_33,q3),r4_s), 7)            \
        TERMP(PADD(PADD(r2_33,a3),r4_33), PADD(PADD(r2_s,q3),r4_33), 7)            \
        TERMP(PADD(PADD(r2_01,q3),r4_33), PADD(PADD(r2_33,q3),r4_01), 7)           \
        TERMP(PADD(PADD(r2_33,q3),r4_10), PADD(PADD(r2_10,q3),r4_33), 7)           \
    }

// ---------------- init ----------------
__global__ void init_kernel(){
    int t = threadIdx.x;
    if (t < 4) g_tmax[t] = 0;
    if (t < 6) g_vmax[t] = 0;
}

// ---------------- erosion pass A ----------------
__global__ __launch_bounds__(256) void erode_max(const float* __restrict__ psrc,
                                                 const float* __restrict__ gsrc,
                                                 int lvl){
    __shared__ float sW[8], sW2[8];
    const int img = blockIdx.y;
    const float* src;
    if (lvl == 1) src = (img < 8) ? psrc + img*NPIX : gsrc + (img-8)*NPIX;
    else          src = (img < 8) ? g_pe1 + img*NPIX : g_ge1 + (img-8)*NPIX;
    const int tid = threadIdx.x;
    float mt = 0.f, mr = 0.f;
#pragma unroll
    for (int k = 0; k < 4; ++k){
        int base = blockIdx.x*4096 + k*1024 + tid*4;
        int y = base >> 9, x = base & 511;
        float4 mid = *(const float4*)(src + base);
        float4 up  = (y > 0)    ? *(const float4*)(src + base - HW) : make_float4(0,0,0,0);
        float4 dn  = (y < HW-1) ? *(const float4*)(src + base + HW) : make_float4(0,0,0,0);
        float  lf  = (x > 0)    ? src[base - 1] : 0.f;
        float  rt  = (x < 508)  ? src[base + 4] : 0.f;
        float t0 = up.x + dn.x + lf    + mid.y;
        float t1 = up.y + dn.y + mid.x + mid.z;
        float t2 = up.z + dn.z + mid.y + mid.w;
        float t3 = up.w + dn.w + mid.z + rt;
        mt = fmaxf(mt, fmaxf(fmaxf(t0,t1), fmaxf(t2,t3)));
        if (lvl == 1) mr = fmaxf(mr, fmaxf(fmaxf(mid.x,mid.y), fmaxf(mid.z,mid.w)));
    }
#pragma unroll
    for (int o = 16; o > 0; o >>= 1){
        mt = fmaxf(mt, __shfl_xor_sync(0xffffffffu, mt, o));
        mr = fmaxf(mr, __shfl_xor_sync(0xffffffffu, mr, o));
    }
    if ((tid & 31) == 0){ sW[tid>>5] = mt; sW2[tid>>5] = mr; }
    __syncthreads();
    if (tid == 0){
#pragma unroll
        for (int i = 1; i < 8; ++i){ mt = fmaxf(mt, sW[i]); mr = fmaxf(mr, sW2[i]); }
        atomicMax(&g_tmax[2*(lvl-1) + (img < 8 ? 0 : 1)], __float_as_int(mt));
        if (lvl == 1) atomicMax(&g_vmax[img < 8 ? 0 : 3], __float_as_int(mr));
    }
}

// ---------------- erosion pass B ----------------
__global__ __launch_bounds__(256) void erode_finish(const float* __restrict__ psrc,
                                                    const float* __restrict__ gsrc,
                                                    int lvl){
    __shared__ float sW[8];
    const int img = blockIdx.y;
    const float* src;
    float* dst;
    if (lvl == 1){ src = (img < 8) ? psrc + img*NPIX : gsrc + (img-8)*NPIX;
                   dst = (img < 8) ? g_pe1 + img*NPIX : g_ge1 + (img-8)*NPIX; }
    else         { src = (img < 8) ? g_pe1 + img*NPIX : g_ge1 + (img-8)*NPIX;
                   dst = (img < 8) ? g_pe2 + img*NPIX : g_ge2 + (img-8)*NPIX; }
    const int tid = threadIdx.x;
    const float tmax = __int_as_float(g_tmax[2*(lvl-1) + (img < 8 ? 0 : 1)]);
    const float inv = __frcp_rn(tmax + 1e-8f);
    float mv = 0.f;
#pragma unroll
    for (int k = 0; k < 4; ++k){
        int base = blockIdx.x*4096 + k*1024 + tid*4;
        int y = base >> 9, x = base & 511;
        float4 mid = *(const float4*)(src + base);
        float4 up  = (y > 0)    ? *(const float4*)(src + base - HW) : make_float4(0,0,0,0);
        float4 dn  = (y < HW-1) ? *(const float4*)(src + base + HW) : make_float4(0,0,0,0);
        float  lf  = (x > 0)    ? src[base - 1] : 0.f;
        float  rt  = (x < 508)  ? src[base + 4] : 0.f;
        float4 v;
        v.x = sigm10((up.x + dn.x + lf    + mid.y) * inv, 0.7f);
        v.y = sigm10((up.y + dn.y + mid.x + mid.z) * inv, 0.7f);
        v.z = sigm10((up.z + dn.z + mid.y + mid.w) * inv, 0.7f);
        v.w = sigm10((up.w + dn.w + mid.z + rt   ) * inv, 0.7f);
        *(float4*)(dst + base) = v;
        mv = fmaxf(mv, fmaxf(fmaxf(v.x,v.y), fmaxf(v.z,v.w)));
    }
#pragma unroll
    for (int o = 16; o > 0; o >>= 1) mv = fmaxf(mv, __shfl_xor_sync(0xffffffffu, mv, o));
    if ((tid & 31) == 0) sW[tid >> 5] = mv;
    __syncthreads();
    if (tid == 0){
#pragma unroll
        for (int i = 1; i < 8; ++i) mv = fmaxf(mv, sW[i]);
        atomicMax(&g_vmax[(img < 8 ? 0 : 3) + lvl], __float_as_int(mv));
    }
}

// ---------------- unified cp kernel: interior branch + edge branch ----------------
// grid 7584 x NT=256.  bid<4704: interior (z=bid/196, tile rem);  else edge.
// Shared arrays are the union (edge reuses interior's); total = R11's proven 22.7 KB.
__global__ __launch_bounds__(NT, 3) void cp_all_kernel(const float* __restrict__ pred0,
                                                       const float* __restrict__ gt0){
    __shared__ pf    fA[39*PK];
    __shared__ pf    fB[39*PK];
    __shared__ float sS[2][SSN*SSP];
    __shared__ float sW[8];
    const int tid = threadIdx.x;
    const int bid = blockIdx.x;

    if (bid < 4704){
        // ================= interior: merged inv0+inv1 (R11 cp_int body) =================
        const int z   = bid / 196;
        const int rem = bid - z*196;
        const int by  = rem / 14, bx = rem - by*14;
        const int level = z >> 3;
        const int b     = z & 7;
        const int oy = (by + 1) * TS, ox = (bx + 1) * TS;

        float cp[2][2][4];
        for (int ts = 0; ts < 2; ++ts){
            const float* base = (ts == 0)
                ? (level == 0 ? pred0 : (level == 1 ? g_pe1 : g_pe2))
                : (level == 0 ? gt0   : (level == 1 ? g_ge1 : g_ge2));
            const float* src = base + b*NPIX;
            const float vmax = __int_as_float(g_vmax[(ts ? 3 : 0) + level]);
            const float vk = HL2E * vmax;
            const float ih7f  = exp2f(L2E - 7.f*vk);
            const float ih9f  = exp2f(L2E - 9.f*vk);
            const float ih10f = exp2f(L2E - 10.f*vk);
            const float ih11f = exp2f(L2E - 11.f*vk);
            const float ih13f = exp2f(L2E - 13.f*vk);
            const float ih16f = exp2f(L2E - 16.f*vk);
            const pf IH7  = PK2(ih7f,ih7f),   IH9  = PK2(ih9f,ih9f);
            const pf IH10 = PK2(ih10f,ih10f), IH11 = PK2(ih11f,ih11f);
            const pf IH13 = PK2(ih13f,ih13f), IH16 = PK2(ih16f,ih16f);

            float* A = (float*)fA; float* B = (float*)fB;
            for (int i = tid; i < 39*39; i += NT){
                int a = i / 39, c = i - a*39;
                float v = src[(oy - 4 + a)*HW + (ox - 4 + c)] * L2E;
                A[(c*PK + (a >> 1))*2 + (a & 1)] = v;
                if (a & 1)       B[(c*PK + (a >> 1))*2]         = v;
                else if (a >= 2) B[(c*PK + (a >> 1) - 1)*2 + 1] = v;
            }
            __syncthreads();

            for (int idx = tid; idx < 34*17; idx += NT){
                int p = idx / 34, x = idx - p*34;
#define RW(r,c) ( ((r) & 1) ? fB[(x+(c))*PK + p + ((r)>>1)] : fA[(x+(c))*PK + p + ((r)>>1)] )
#define TERMP(eA,eB,k) { pf mA,mnA,mB,mnB; mexp((eA),mA,mnA); mexp((eB),mB,mnB); \
                         npair(mnA,mnB,Sn); ipair(mA,mB,IH##k,Si); }
#define TERMS(e,k)     { pf m,mn; mexp((e),m,mn); nsingle(mn,Sn); isingle(m,IH##k,Si); }
                pf Sn = 0ull, Si = 0ull;
                TREE_BODY2
                float S0n,S1n,S0i,S1i; UPK(Sn,S0n,S1n); UPK(Si,S0i,S1i);
                float w0,w1; UPK(RW(3,3), w0, w1);
#undef TERMP
#undef TERMS
#undef RW
                float c00 = w0 * IL2E, c01 = w1 * IL2E;
                int sy = 2*p;
                sS[0][sy*SSP + x]     = sigm10(c00*S0n, 0.5f);
                sS[0][(sy+1)*SSP + x] = sigm10(c01*S1n, 0.5f);
                sS[1][sy*SSP + x]     = sigm10((vmax - c00)*S0i, 0.5f);
                sS[1][(sy+1)*SSP + x] = sigm10((vmax - c01)*S1i, 0.5f);
            }
            __syncthreads();

            // dilate both variants: 2048 outputs = 8 * 256, exactly uniform
            for (int idx = tid, j = 0; idx < 2048; idx += NT, ++j){
                int v = idx >> 10, r = idx & 1023;
                int ly = r >> 5, lx = r & 31;
                float acc = 0.f;
#pragma unroll
                for (int dy = 0; dy < 3; ++dy)
#pragma unroll
                    for (int dx = 0; dx < 3; ++dx)
                        acc += sS[v][(ly+dy)*SSP + lx + dx];
                acc = fminf(fmaxf(acc, 0.f), 1.f);
                cp[ts][j >> 2][j & 3] = acc;
            }
            __syncthreads();
        }

        float local = 0.f;
#pragma unroll
        for (int v = 0; v < 2; ++v)
#pragma unroll
        for (int q = 0; q < 4; ++q){
            float d = cp[0][v][q] - cp[1][v][q];
            local += d*d;
        }
#pragma unroll
        for (int o = 16; o > 0; o >>= 1) local += __shfl_xor_sync(0xffffffffu, local, o);
        if ((tid & 31) == 0) sW[tid >> 5] = local;
        __syncthreads();
        if (tid == 0){
            float s = sW[0];
#pragma unroll
            for (int i = 1; i < 8; ++i) s += sW[i];
            g_partial[bid] = s;
        }
    } else {
        // ================= edge: general path (R11 cp_edge body) =================
        const int e  = bid - 4704;
        const int z  = e / 60;
        const int t  = e - z*60;
        const int pt = z >> 3;
        const int b  = z & 7;
        const int level = pt >> 1;
        const int inv   = pt & 1;
        int bx, by;
        if      (t < 16){ bx = t;      by = 0;      }
        else if (t < 32){ bx = t - 16; by = 15;     }
        else if (t < 46){ bx = 0;      by = t - 31; }
        else            { bx = 15;     by = t - 45; }
        const int oy = by * TS, ox = bx * TS;

        float cp[2][4];
        for (int ts = 0; ts < 2; ++ts){
            const float* base = (ts == 0)
                ? (level == 0 ? pred0 : (level == 1 ? g_pe1 : g_pe2))
                : (level == 0 ? gt0   : (level == 1 ? g_ge1 : g_ge2));
            const float* src = base + b*NPIX;
            float vmax = inv ? __int_as_float(g_vmax[(ts ? 3 : 0) + level]) : 0.f;

            float* A = (float*)fA; float* B = (float*)fB;
            for (int i = tid; i < 39*39; i += NT){
                int a = i / 39, c = i - a*39;
                int qy = oy - 4 + a, qx = ox - 4 + c;
                float v;
                if (qy < -1 || qy > HW || qx < -1 || qx > HW) v = 0.f;
                else if (qy == -1 || qy == HW || qx == -1 || qx == HW) v = L2E;
                else { float u = src[qy*HW + qx]; v = (inv ? vmax - u : u) * L2E; }
                A[(c*PK + (a >> 1))*2 + (a & 1)] = v;
                if (a & 1)       B[(c*PK + (a >> 1))*2]         = v;
                else if (a >= 2) B[(c*PK + (a >> 1) - 1)*2 + 1] = v;
            }
            __syncthreads();

            for (int idx = tid; idx < 34*17; idx += NT){
                int p = idx / 34, x = idx - p*34;
#define RW(r,c) ( ((r) & 1) ? fB[(x+(c))*PK + p + ((r)>>1)] : fA[(x+(c))*PK + p + ((r)>>1)] )
#define TERMP(eA,eB,k) { pf mA,mnA,mB,mnB; mexp((eA),mA,mnA); mexp((eB),mB,mnB); \
                         npair(mnA,mnB,Sn); }
#define TERMS(e,k)     { pf m,mn; mexp((e),m,mn); nsingle(mn,Sn); }
                pf Sn = 0ull;
                TREE_BODY2
                float S0,S1; UPK(Sn,S0,S1);
                float w0,w1; UPK(RW(3,3), w0, w1);
#undef TERMP
#undef TERMS
#undef RW
                float c00 = w0 * IL2E, c01 = w1 * IL2E;
                int sy = 2*p;
                int gy0 = oy + sy - 1, gx = ox + x - 1;
                float s0 = sigm10(c00*S0, 0.5f);
                float s1 = sigm10(c01*S1, 0.5f);
                bool okx = ((unsigned)gx < HW);
                if (!okx || (unsigned)gy0     >= HW) s0 = 0.f;
                if (!okx || (unsigned)(gy0+1) >= HW) s1 = 0.f;
                sS[0][sy*SSP + x]     = s0;
                sS[0][(sy+1)*SSP + x] = s1;
            }
            __syncthreads();

#pragma unroll
            for (int q = 0; q < 4; ++q){
                int ly = (tid >> 5) + q*8, lx = tid & 31;
                float acc = 0.f;
#pragma unroll
                for (int dy = 0; dy < 3; ++dy)
#pragma unroll
                    for (int dx = 0; dx < 3; ++dx)
                        acc += sS[0][(ly+dy)*SSP + lx + dx];
                cp[ts][q] = fminf(fmaxf(acc, 0.f), 1.f);
            }
            __syncthreads();
        }

        float local = 0.f;
#pragma unroll
        for (int q = 0; q < 4; ++q){
            float d = cp[0][q] - cp[1][q];
            local += d*d;
        }
#pragma unroll
        for (int o = 16; o > 0; o >>= 1) local += __shfl_xor_sync(0xffffffffu, local, o);
        if ((tid & 31) == 0) sW[tid >> 5] = local;
        __syncthreads();
        if (tid == 0){
            float s = sW[0];
#pragma unroll
            for (int i = 1; i < 8; ++i) s += sW[i];
            g_partial[bid] = s;
        }
    }
}

// ---------------- deterministic final reduction ----------------
__global__ __launch_bounds__(256) void final_kernel(float* out){
    __shared__ double sh[256];
    double a = 0.0;
    for (int i = threadIdx.x; i < 7584; i += 256) a += (double)g_partial[i];
    sh[threadIdx.x] = a; __syncthreads();
    for (int o = 128; o > 0; o >>= 1){
        if (threadIdx.x < o) sh[threadIdx.x] += sh[threadIdx.x+o];
        __syncthreads();
    }
    if (threadIdx.x == 0) out[0] = (float)(sh[0] * 0.125);
}

// ---------------- launch ----------------
extern "C" void kernel_launch(void* const* d_in, const int* in_sizes, int n_in,
                              void* d_out, int out_size){
    const float* pred = (const float*)d_in[0];
    const float* gt   = (const float*)d_in[1];
    float* out = (float*)d_out;
    (void)in_sizes; (void)n_in; (void)out_size;

    init_kernel<<<1, 32>>>();
    erode_max   <<<dim3(64, 16), 256>>>(pred, gt, 1);
    erode_finish<<<dim3(64, 16), 256>>>(pred, gt, 1);
    erode_max   <<<dim3(64, 16), 256>>>(pred, gt, 2);
    erode_finish<<<dim3(64, 16), 256>>>(pred, gt, 2);
    cp_all_kernel<<<7584, NT>>>(pred, gt);
    final_kernel<<<1, 256>>>(out);
}